// round 8
// baseline (speedup 1.0000x reference)
#include <cuda_runtime.h>
#include <cuda_bf16.h>
#include <math.h>

// Problem constants
#define BB   4
#define NN   128
#define DIM  256
#define HH   8
#define DHH  64
#define EE   64
#define INNER 512
#define ROWS 512          // B*N
#define LN10000 9.210340371976184f

// ---------------- scratch (one big static device buffer) ----------------
#define E_OFF     0            // 4*128*128*64 = 4194304  (edge LN result, (b,i,j,c))
#define NODES_OFF 4194304      // 131072
#define XN_OFF    4325376      // 131072
#define XE_OFF    4456448      // 262144 (also VQ scores 512x512)
#define QKV_OFF   4718592      // 512*1536 = 786432  [Q | K | V] rotated
#define QW_OFF    5505024      // 262144  (b,i,h,c)
#define SIME_OFF  5767168      // 524288  (b,i,j,h)
#define ATT_OFF   6291456      // 524288  (b,i,h,j)
#define AOUT_OFF  6815744      // 262144
#define OUT2_OFF  7077888      // 131072
#define H1_OFF    7208960      // 524288
#define H2_OFF    7733248      // 131072
#define CN_OFF    7864320      // 512
#define SCRATCH_FLOATS 7864832

__device__ float g_scratch[SCRATCH_FLOATS];

// ---------------- reductions ----------------
__device__ __forceinline__ float blockSum256(float v, float* red8) {
    int lane = threadIdx.x & 31, w = threadIdx.x >> 5;
#pragma unroll
    for (int o = 16; o; o >>= 1) v += __shfl_xor_sync(0xffffffffu, v, o);
    if (!lane) red8[w] = v;
    __syncthreads();
    float t = (threadIdx.x < 8) ? red8[threadIdx.x] : 0.f;
    if (w == 0) {
#pragma unroll
        for (int o = 4; o; o >>= 1) t += __shfl_xor_sync(0xffffffffu, t, o);
        if (!lane) red8[0] = t;
    }
    __syncthreads();
    v = red8[0];
    __syncthreads();
    return v;
}

// ---------------- edge LayerNorm: edges (B,E,N,N) -> e (B,N,N,E) ----------------
__global__ void edge_ln_kernel(const float* __restrict__ edges,
                               const float* __restrict__ g, const float* __restrict__ b,
                               float* __restrict__ e) {
    __shared__ float s[64 * 129];
    __shared__ float mn[128], rs[128];
    int bi = blockIdx.x;              // b*128 + i
    int bidx = bi >> 7, i = bi & 127;
    int tid = threadIdx.x;
    for (int idx = tid; idx < 8192; idx += 256) {
        int c = idx >> 7, j = idx & 127;
        s[c * 129 + j] = edges[((bidx * 64 + c) * 128 + i) * 128 + j];
    }
    __syncthreads();
    if (tid < 128) {
        int j = tid;
        float sum = 0.f;
#pragma unroll 16
        for (int c = 0; c < 64; c++) sum += s[c * 129 + j];
        float m = sum * (1.f / 64.f);
        float var = 0.f;
#pragma unroll 16
        for (int c = 0; c < 64; c++) { float d = s[c * 129 + j] - m; var += d * d; }
        var *= (1.f / 64.f);
        mn[j] = m;
        rs[j] = rsqrtf(var + 1e-5f);
    }
    __syncthreads();
    float* ep = e + (size_t)bi * 8192;
    for (int idx = tid; idx < 8192; idx += 256) {
        int j = idx >> 6, c = idx & 63;
        ep[idx] = (s[c * 129 + j] - mn[j]) * rs[j] * g[c] + b[c];
    }
}

// ---------------- row LayerNorm over 256 ----------------
__global__ void ln_rows_kernel(const float* __restrict__ in,
                               const float* __restrict__ g, const float* __restrict__ b,
                               float* __restrict__ out) {
    __shared__ float red[8];
    int row = blockIdx.x, t = threadIdx.x;
    float x = in[row * 256 + t];
    float m = blockSum256(x, red) * (1.f / 256.f);
    float d = x - m;
    float var = blockSum256(d * d, red) * (1.f / 256.f);
    out[row * 256 + t] = d * rsqrtf(var + 1e-5f) * g[t] + b[t];
}

// ---------------- GEMM: 64 threads, BM = 8*TM, BN = 32, KB = 16 ----------------
// MODE 0: C = A@W + bias
// MODE 1: C = gelu(A@W + bias)
// MODE 2: QKV combined: cols [0,512) -> W (ldw), cols [512,1536) -> W2 (ldw2),
//         bias/bias2 likewise; rotary applied to cols < 1024.
// MODE 3: C = A @ W^T (W row-major N x K), no bias (VQ scores)
template<int MODE, int TM>
__global__ __launch_bounds__(64) void gemm_kernel(
        const float* __restrict__ A, const float* __restrict__ W,
        const float* __restrict__ W2,
        const float* __restrict__ bias, const float* __restrict__ bias2,
        float* __restrict__ C, int N, int K, int ldw, int ldw2) {
    constexpr int BM = TM * 8;
    constexpr int APAD = BM + 4;          // floats per As row
    __shared__ __align__(16) float As[16 * APAD];
    __shared__ __align__(16) float Bs[16 * 36];
    int tid = threadIdx.x;
    int tx = tid & 7, ty = tid >> 3;
    int mo = blockIdx.y * BM, no = blockIdx.x * 32;

    // block-scope W / bias selection (MODE 2)
    const float* Wb = W;
    const float* bp = bias;
    int ld = ldw, noff = no;
    if (MODE == 2 && no >= 512) { Wb = W2; ld = ldw2; noff = no - 512; bp = bias2 - 512; }

    float acc[TM][4];
#pragma unroll
    for (int u = 0; u < TM; u++)
#pragma unroll
        for (int v = 0; v < 4; v++) acc[u][v] = 0.f;

    for (int k0 = 0; k0 < K; k0 += 16) {
        // load A tile (BM x 16), store transposed As[k][m]
#pragma unroll
        for (int l = 0; l < BM / 16; l++) {
            int q = tid + l * 64;                 // 0 .. BM*4-1
            int row = q >> 2, c4 = q & 3;
            float4 f = *(const float4*)&A[(mo + row) * K + k0 + c4 * 4];
            As[(c4 * 4 + 0) * APAD + row] = f.x;
            As[(c4 * 4 + 1) * APAD + row] = f.y;
            As[(c4 * 4 + 2) * APAD + row] = f.z;
            As[(c4 * 4 + 3) * APAD + row] = f.w;
        }
        // load B tile (16 x 32)
        if (MODE != 3) {
#pragma unroll
            for (int l = 0; l < 2; l++) {
                int q = tid + l * 64;             // 0..127
                int r = q >> 3, c4 = q & 7;
                float4 f = *(const float4*)&Wb[(k0 + r) * ld + noff + c4 * 4];
                *(float4*)&Bs[r * 36 + c4 * 4] = f;
            }
        } else {
#pragma unroll
            for (int l = 0; l < 2; l++) {
                int q = tid + l * 64;             // 0..127
                int c = q >> 2, r4 = q & 3;
                float4 f = *(const float4*)&W[(no + c) * K + k0 + r4 * 4];
                Bs[(r4 * 4 + 0) * 36 + c] = f.x;
                Bs[(r4 * 4 + 1) * 36 + c] = f.y;
                Bs[(r4 * 4 + 2) * 36 + c] = f.z;
                Bs[(r4 * 4 + 3) * 36 + c] = f.w;
            }
        }
        __syncthreads();
#pragma unroll
        for (int kk = 0; kk < 16; kk++) {
            float a[TM];
            if (TM == 8) {
                float4 a0 = *(const float4*)&As[kk * APAD + ty * 8];
                float4 a1 = *(const float4*)&As[kk * APAD + ty * 8 + 4];
                a[0] = a0.x; a[1] = a0.y; a[2] = a0.z; a[3] = a0.w;
                a[4] = a1.x; a[5] = a1.y; a[6] = a1.z; a[7] = a1.w;
            } else {
                float4 a0 = *(const float4*)&As[kk * APAD + ty * 4];
                a[0] = a0.x; a[1] = a0.y; a[2] = a0.z; a[3] = a0.w;
            }
            float4 b4 = *(const float4*)&Bs[kk * 36 + tx * 4];
            float b[4] = {b4.x, b4.y, b4.z, b4.w};
#pragma unroll
            for (int u = 0; u < TM; u++)
#pragma unroll
                for (int v = 0; v < 4; v++) acc[u][v] += a[u] * b[v];
        }
        __syncthreads();
    }

    int col = no + tx * 4;
    // rotary angle factors (depend only on column) for MODE 2
    float inv0 = 0.f, inv1 = 0.f;
    bool do_rot = (MODE == 2) && (no < 1024);
    if (MODE == 2 && do_rot) {
        int d0 = col & 63;                        // even
        inv0 = expf(-((float)d0 / 64.f) * LN10000);
        inv1 = expf(-((float)(d0 + 2) / 64.f) * LN10000);
    }
#pragma unroll
    for (int u = 0; u < TM; u++) {
        int row = mo + ty * TM + u;
        float4 r;
        r.x = acc[u][0]; r.y = acc[u][1]; r.z = acc[u][2]; r.w = acc[u][3];
        if (MODE != 3) {
            r.x += bp[col]; r.y += bp[col + 1]; r.z += bp[col + 2]; r.w += bp[col + 3];
        }
        if (MODE == 1) {
            r.x = 0.5f * r.x * (1.f + erff(r.x * 0.70710678118654752f));
            r.y = 0.5f * r.y * (1.f + erff(r.y * 0.70710678118654752f));
            r.z = 0.5f * r.z * (1.f + erff(r.z * 0.70710678118654752f));
            r.w = 0.5f * r.w * (1.f + erff(r.w * 0.70710678118654752f));
        }
        if (MODE == 2 && do_rot) {
            float n = (float)(row & 127);
            float s0, c0, s1, c1;
            sincosf(n * inv0, &s0, &c0);
            sincosf(n * inv1, &s1, &c1);
            float x1 = r.x, x2 = r.y;
            r.x = x1 * c0 - x2 * s0;
            r.y = x2 * c0 + x1 * s0;
            x1 = r.z; x2 = r.w;
            r.z = x1 * c1 - x2 * s1;
            r.w = x2 * c1 + x1 * s1;
        }
        *(float4*)&C[row * N + col] = r;
    }
}

// ---------------- qw[b,i,h,c] = sum_d qrot[b,i,h*64+d] * w_ekv[c, h*64+d] ----------------
__global__ void qw_kernel(const float* __restrict__ qkv, const float* __restrict__ wekv,
                          float* __restrict__ qw) {
    __shared__ float qs[64];
    int bi = blockIdx.x, h = blockIdx.y;
    int tid = threadIdx.x;
    qs[tid] = qkv[bi * 1536 + h * 64 + tid];
    __syncthreads();
    float s = 0.f;
    const float* wr = wekv + tid * 512 + h * 64;
#pragma unroll 16
    for (int d = 0; d < 64; d++) s += qs[d] * wr[d];
    qw[(bi * 8 + h) * 64 + tid] = s;
}

// ---------------- sim_e[b,i,j,h] = sum_c qw[b,i,h,c] * e[b,i,j,c] ----------------
__global__ void sime_kernel(const float* __restrict__ e, const float* __restrict__ qw,
                            float* __restrict__ sime) {
    __shared__ float esm[128 * 65];
    __shared__ float qwsm[8 * 66];
    int bi = blockIdx.x, tid = threadIdx.x;
    const float* ep = e + (size_t)bi * 8192;
    for (int idx = tid; idx < 8192; idx += 256) {
        int j = idx >> 6, c = idx & 63;
        esm[j * 65 + c] = ep[idx];
    }
    for (int idx = tid; idx < 512; idx += 256) {
        int h = idx >> 6, c = idx & 63;
        qwsm[h * 66 + c] = qw[bi * 512 + idx];
    }
    __syncthreads();
    for (int idx = tid; idx < 1024; idx += 256) {
        int h = idx & 7, j = idx >> 3;
        float s = 0.f;
#pragma unroll 16
        for (int c = 0; c < 64; c++) s += qwsm[h * 66 + c] * esm[j * 65 + c];
        sime[bi * 1024 + idx] = s;
    }
}

// ---------------- attention core: per (b,h), chunk of 16 i ----------------
#define ATTN_SMEM ((128*65 + 128*64) * 4)
__global__ void attn_kernel(const float* __restrict__ qkv,
                            const float* __restrict__ sime,
                            float* __restrict__ att, float* __restrict__ aout) {
    extern __shared__ float dyn[];
    float* ksm = dyn;                 // 128*65
    float* vsm = dyn + 128 * 65;      // 128*64
    __shared__ float qs[64], attsm[128], psm[128], redm[4], reds[4];
    int bh = blockIdx.x;
    int b = bh >> 3, h = bh & 7;
    int i0 = blockIdx.y * 16;
    int tid = threadIdx.x, lane = tid & 31, w = tid >> 5;
    for (int idx = tid; idx < 8192; idx += 128) {
        int j = idx >> 6, d = idx & 63;
        ksm[j * 65 + d] = qkv[(b * 128 + j) * 1536 + 512 + h * 64 + d];
        vsm[j * 64 + d] = qkv[(b * 128 + j) * 1536 + 1024 + h * 64 + d];
    }
    __syncthreads();
    for (int ii = 0; ii < 16; ii++) {
        int i = i0 + ii;
        int bi = b * 128 + i;
        if (tid < 64) qs[tid] = qkv[bi * 1536 + h * 64 + tid];
        __syncthreads();
        int j = tid;
        float sim = sime[(bi * 128 + j) * 8 + h];
#pragma unroll 16
        for (int d = 0; d < 64; d++) sim += qs[d] * ksm[j * 65 + d];
        sim *= 0.125f;
        float m = sim;
#pragma unroll
        for (int o = 16; o; o >>= 1) m = fmaxf(m, __shfl_xor_sync(0xffffffffu, m, o));
        if (!lane) redm[w] = m;
        __syncthreads();
        m = fmaxf(fmaxf(redm[0], redm[1]), fmaxf(redm[2], redm[3]));
        float ex = expf(sim - m);
        float s = ex;
#pragma unroll
        for (int o = 16; o; o >>= 1) s += __shfl_xor_sync(0xffffffffu, s, o);
        if (!lane) reds[w] = s;
        __syncthreads();
        s = reds[0] + reds[1] + reds[2] + reds[3];
        float a = ex / s;
        attsm[tid] = a;
        att[(bi * 8 + h) * 128 + tid] = a;
        __syncthreads();
        int gg = tid >> 6, d = tid & 63;
        float acc = 0.f;
#pragma unroll 16
        for (int jj = 0; jj < 64; jj++) acc += attsm[gg * 64 + jj] * vsm[(gg * 64 + jj) * 64 + d];
        psm[tid] = acc;
        __syncthreads();
        if (tid < 64) aout[bi * 512 + h * 64 + tid] = psm[tid] + psm[64 + tid];
        __syncthreads();
    }
}

// ---------------- edge output: ae = att @ e ; aout += ae @ w_ekv + b_ekv ----------------
__global__ void edgeout_kernel(const float* __restrict__ e, const float* __restrict__ att,
                               const float* __restrict__ wekv, const float* __restrict__ bekv,
                               float* __restrict__ aout) {
    __shared__ float esm[128 * 65];
    __shared__ float asmem[8 * 128];
    __shared__ float aesm[8 * 66];
    int bi = blockIdx.x, tid = threadIdx.x;
    const float* ep = e + (size_t)bi * 8192;
    for (int idx = tid; idx < 8192; idx += 256) {
        int j = idx >> 6, c = idx & 63;
        esm[j * 65 + c] = ep[idx];
    }
    for (int idx = tid; idx < 1024; idx += 256) asmem[idx] = att[bi * 1024 + idx];
    __syncthreads();
    for (int idx = tid; idx < 512; idx += 256) {
        int h = idx >> 6, c = idx & 63;
        float s = 0.f;
#pragma unroll 16
        for (int j = 0; j < 128; j++) s += asmem[h * 128 + j] * esm[j * 65 + c];
        aesm[h * 66 + c] = s;
    }
    __syncthreads();
    for (int idx = tid; idx < 512; idx += 256) {
        int h = idx >> 6, d = idx & 63;
        float s = bekv[idx];
#pragma unroll 16
        for (int c = 0; c < 64; c++) s += aesm[h * 66 + c] * wekv[c * 512 + h * 64 + d];
        aout[bi * 512 + idx] += s;
    }
}

// ---------------- gated residual (in-place) + optional fused LayerNorm ----------------
__global__ void gate_ln_kernel(const float* __restrict__ x, float* __restrict__ nodes,
                               const float* __restrict__ gw,
                               const float* __restrict__ lng, const float* __restrict__ lnb,
                               float* __restrict__ lnout) {
    __shared__ float red[8];
    int row = blockIdx.x, t = threadIdx.x;
    float xv = x[row * 256 + t];
    float rv = nodes[row * 256 + t];
    float contrib = xv * gw[t] + rv * gw[256 + t] + (xv - rv) * gw[512 + t];
    float s = blockSum256(contrib, red);
    float gate = 1.f / (1.f + expf(-s));
    float nn = xv * gate + rv * (1.f - gate);
    nodes[row * 256 + t] = nn;
    if (lng) {
        float m = blockSum256(nn, red) * (1.f / 256.f);
        float d = nn - m;
        float var = blockSum256(d * d, red) * (1.f / 256.f);
        lnout[row * 256 + t] = d * rsqrtf(var + 1e-5f) * lng[t] + lnb[t];
    }
}

// ---------------- codebook squared norms ----------------
__global__ void cnorm_kernel(const float* __restrict__ cb, float* __restrict__ cn) {
    __shared__ float red[8];
    int k = blockIdx.x, t = threadIdx.x;
    float v = cb[k * 256 + t];
    float s = blockSum256(v * v, red);
    if (!t) cn[k] = s;
}

// ---------------- argmin + gather ----------------
__global__ void vq_kernel(const float* __restrict__ S, const float* __restrict__ cn,
                          const float* __restrict__ cb, const float* __restrict__ z,
                          float* __restrict__ out) {
    __shared__ float bv[256];
    __shared__ int bix[256];
    int r = blockIdx.x, t = threadIdx.x;
    float best = 1e30f; int bidx = 0;
    for (int k = t; k < 512; k += 256) {
        float v = cn[k] - 2.f * S[r * 512 + k];
        if (v < best) { best = v; bidx = k; }
    }
    bv[t] = best; bix[t] = bidx;
    __syncthreads();
    for (int s = 128; s; s >>= 1) {
        if (t < s) {
            float v2 = bv[t + s]; int i2 = bix[t + s];
            if (v2 < bv[t] || (v2 == bv[t] && i2 < bix[t])) { bv[t] = v2; bix[t] = i2; }
        }
        __syncthreads();
    }
    int k = bix[0];
    float zz = z[r * 256 + t];
    out[r * 256 + t] = zz + (cb[k * 256 + t] - zz);
}

// ---------------- host launch ----------------
extern "C" void kernel_launch(void* const* d_in, const int* in_sizes, int n_in,
                              void* d_out, int out_size) {
    const float* in_nodes = (const float*)d_in[0];
    const float* edges   = (const float*)d_in[1];
    const float* eg      = (const float*)d_in[2];
    const float* ebias   = (const float*)d_in[3];
    const float* ln1g    = (const float*)d_in[4];
    const float* ln1b    = (const float*)d_in[5];
    const float* wexp    = (const float*)d_in[6];
    const float* bexp    = (const float*)d_in[7];
    const float* wq      = (const float*)d_in[8];
    const float* bq      = (const float*)d_in[9];
    const float* wkv     = (const float*)d_in[10];
    const float* bkv     = (const float*)d_in[11];
    const float* wekv    = (const float*)d_in[12];
    const float* bekv    = (const float*)d_in[13];
    const float* wout    = (const float*)d_in[14];
    const float* bout    = (const float*)d_in[15];
    const float* g1      = (const float*)d_in[16];
    const float* ln2g    = (const float*)d_in[17];
    const float* ln2b    = (const float*)d_in[18];
    const float* wff1    = (const float*)d_in[19];
    const float* bff1    = (const float*)d_in[20];
    const float* wff2    = (const float*)d_in[21];
    const float* bff2    = (const float*)d_in[22];
    const float* g2      = (const float*)d_in[23];
    const float* cb      = (const float*)d_in[24];
    float* out = (float*)d_out;

    float* S;
    cudaGetSymbolAddress((void**)&S, g_scratch);
    float* E     = S + E_OFF;
    float* NODES = S + NODES_OFF;
    float* XN    = S + XN_OFF;
    float* XE    = S + XE_OFF;
    float* QKV   = S + QKV_OFF;
    float* QW    = S + QW_OFF;
    float* SIME  = S + SIME_OFF;
    float* ATT   = S + ATT_OFF;
    float* AOUT  = S + AOUT_OFF;
    float* OUT2  = S + OUT2_OFF;
    float* H1    = S + H1_OFF;
    float* H2    = S + H2_OFF;
    float* CN    = S + CN_OFF;

    cudaFuncSetAttribute(attn_kernel, cudaFuncAttributeMaxDynamicSharedMemorySize, ATTN_SMEM);

    cudaMemcpyAsync(NODES, in_nodes, (size_t)ROWS * 256 * sizeof(float),
                    cudaMemcpyDeviceToDevice);

    edge_ln_kernel<<<512, 256>>>(edges, eg, ebias, E);
    ln_rows_kernel<<<512, 256>>>(NODES, ln1g, ln1b, XN);

    for (int l = 0; l < 2; l++) {
        // XE = XN @ wexp + bexp          (512x512, K=256)
        gemm_kernel<0, 8><<<dim3(16, 8), 64>>>(XN, wexp + l * 131072, nullptr,
                                               bexp + l * 512, nullptr, XE, 512, 256, 512, 0);
        // QKV = XE @ [wq | wkv] + bias, rotary on Q,K   (512x1536, K=512)
        gemm_kernel<2, 8><<<dim3(48, 8), 64>>>(XE, wq + l * 262144, wkv + l * 524288,
                                               bq + l * 512, bkv + l * 1024, QKV,
                                               1536, 512, 512, 1024);
        qw_kernel<<<dim3(512, 8), 64>>>(QKV, wekv + l * 32768, QW);
        sime_kernel<<<512, 256>>>(E, QW, SIME);
        attn_kernel<<<dim3(32, 8), 128, ATTN_SMEM>>>(QKV, SIME, ATT, AOUT);
        edgeout_kernel<<<512, 256>>>(E, ATT, wekv + l * 32768, bekv + l * 512, AOUT);
        // OUT2 = AOUT @ wout + bout      (512x256, K=512)
        gemm_kernel<0, 4><<<dim3(8, 16), 64>>>(AOUT, wout + l * 131072, nullptr,
                                               bout + l * 256, nullptr, OUT2, 256, 512, 256, 0);
        gate_ln_kernel<<<512, 256>>>(OUT2, NODES, g1 + l * 768,
                                     ln2g + l * 256, ln2b + l * 256, XN);
        // H1 = gelu(XN @ wff1 + bff1)    (512x1024, K=256)
        gemm_kernel<1, 8><<<dim3(32, 8), 64>>>(XN, wff1 + l * 262144, nullptr,
                                               bff1 + l * 1024, nullptr, H1, 1024, 256, 1024, 0);
        // H2 = H1 @ wff2 + bff2          (512x256, K=1024)
        gemm_kernel<0, 4><<<dim3(8, 16), 64>>>(H1, wff2 + l * 262144, nullptr,
                                               bff2 + l * 256, nullptr, H2, 256, 1024, 256, 0);
        if (l == 0) {
            gate_ln_kernel<<<512, 256>>>(H2, NODES, g2 + l * 768,
                                         ln1g + 256, ln1b + 256, XN);
        } else {
            gate_ln_kernel<<<512, 256>>>(H2, NODES, g2 + l * 768,
                                         nullptr, nullptr, nullptr);
        }
    }

    cnorm_kernel<<<512, 256>>>(cb, CN);
    // VQ scores: S = NODES @ cb^T        (512x512, K=256)
    gemm_kernel<3, 8><<<dim3(16, 8), 64>>>(NODES, cb, nullptr, nullptr, nullptr,
                                           XE, 512, 256, 0, 0);
    vq_kernel<<<512, 256>>>(XE, CN, cb, NODES, out);
}

// round 9
// speedup vs baseline: 1.0018x; 1.0018x over previous
#include <cuda_runtime.h>
#include <cuda_bf16.h>
#include <math.h>

// Problem constants
#define BB   4
#define NN   128
#define DIM  256
#define HH   8
#define DHH  64
#define EE   64
#define INNER 512
#define ROWS 512          // B*N
#define LN10000 9.210340371976184f

// ---------------- scratch (one big static device buffer) ----------------
#define E_OFF     0            // 4*128*128*64 = 4194304  (edge LN result, (b,i,j,c))
#define NODES_OFF 4194304      // 131072
#define XN_OFF    4325376      // 131072
#define XE_OFF    4456448      // 262144 (also VQ scores 512x512)
#define QKV_OFF   4718592      // 512*1536 = 786432  [Q | K | V] rotated
#define QW_OFF    5505024      // 262144  (b,i,h,c)
#define SIME_OFF  5767168      // 524288  (b,i,j,h)
#define ATT_OFF   6291456      // 524288  (b,i,h,j)
#define AOUT_OFF  6815744      // 262144
#define OUT2_OFF  7077888      // 131072
#define H1_OFF    7208960      // 524288
#define H2_OFF    7733248      // 131072
#define CN_OFF    7864320      // 512
#define SCRATCH_FLOATS 7864832

__device__ float g_scratch[SCRATCH_FLOATS];

// ---------------- reductions ----------------
__device__ __forceinline__ float blockSum256(float v, float* red8) {
    int lane = threadIdx.x & 31, w = threadIdx.x >> 5;
#pragma unroll
    for (int o = 16; o; o >>= 1) v += __shfl_xor_sync(0xffffffffu, v, o);
    if (!lane) red8[w] = v;
    __syncthreads();
    float t = (threadIdx.x < 8) ? red8[threadIdx.x] : 0.f;
    if (w == 0) {
#pragma unroll
        for (int o = 4; o; o >>= 1) t += __shfl_xor_sync(0xffffffffu, t, o);
        if (!lane) red8[0] = t;
    }
    __syncthreads();
    v = red8[0];
    __syncthreads();
    return v;
}

// ---------------- edge LayerNorm: edges (B,E,N,N) -> e (B,N,N,E) ----------------
__global__ void edge_ln_kernel(const float* __restrict__ edges,
                               const float* __restrict__ g, const float* __restrict__ b,
                               float* __restrict__ e) {
    __shared__ float s[64 * 129];
    __shared__ float mn[128], rs[128];
    int bi = blockIdx.x;              // b*128 + i
    int bidx = bi >> 7, i = bi & 127;
    int tid = threadIdx.x;
    for (int idx = tid; idx < 8192; idx += 256) {
        int c = idx >> 7, j = idx & 127;
        s[c * 129 + j] = edges[((bidx * 64 + c) * 128 + i) * 128 + j];
    }
    __syncthreads();
    if (tid < 128) {
        int j = tid;
        float sum = 0.f;
#pragma unroll 16
        for (int c = 0; c < 64; c++) sum += s[c * 129 + j];
        float m = sum * (1.f / 64.f);
        float var = 0.f;
#pragma unroll 16
        for (int c = 0; c < 64; c++) { float d = s[c * 129 + j] - m; var += d * d; }
        var *= (1.f / 64.f);
        mn[j] = m;
        rs[j] = rsqrtf(var + 1e-5f);
    }
    __syncthreads();
    float* ep = e + (size_t)bi * 8192;
    for (int idx = tid; idx < 8192; idx += 256) {
        int j = idx >> 6, c = idx & 63;
        ep[idx] = (s[c * 129 + j] - mn[j]) * rs[j] * g[c] + b[c];
    }
}

// ---------------- row LayerNorm over 256 ----------------
__global__ void ln_rows_kernel(const float* __restrict__ in,
                               const float* __restrict__ g, const float* __restrict__ b,
                               float* __restrict__ out) {
    __shared__ float red[8];
    int row = blockIdx.x, t = threadIdx.x;
    float x = in[row * 256 + t];
    float m = blockSum256(x, red) * (1.f / 256.f);
    float d = x - m;
    float var = blockSum256(d * d, red) * (1.f / 256.f);
    out[row * 256 + t] = d * rsqrtf(var + 1e-5f) * g[t] + b[t];
}

// ---------------- GEMM: 64 threads, BM = 8*TM, BN = 32, KB = 16 ----------------
// MODE 0: C = A@W + bias
// MODE 1: C = gelu(A@W + bias)
// MODE 2: QKV combined: cols [0,512) -> W (ldw), cols [512,1536) -> W2 (ldw2),
//         bias/bias2 likewise; rotary applied to cols < 1024.
// MODE 3: C = A @ W^T (W row-major N x K), no bias (VQ scores)
template<int MODE, int TM>
__global__ __launch_bounds__(64) void gemm_kernel(
        const float* __restrict__ A, const float* __restrict__ W,
        const float* __restrict__ W2,
        const float* __restrict__ bias, const float* __restrict__ bias2,
        float* __restrict__ C, int N, int K, int ldw, int ldw2) {
    constexpr int BM = TM * 8;
    constexpr int APAD = BM + 4;          // floats per As row
    __shared__ __align__(16) float As[16 * APAD];
    __shared__ __align__(16) float Bs[16 * 36];
    int tid = threadIdx.x;
    int tx = tid & 7, ty = tid >> 3;
    int mo = blockIdx.y * BM, no = blockIdx.x * 32;

    // block-scope W / bias selection (MODE 2)
    const float* Wb = W;
    const float* bp = bias;
    int ld = ldw, noff = no;
    if (MODE == 2 && no >= 512) { Wb = W2; ld = ldw2; noff = no - 512; bp = bias2 - 512; }

    float acc[TM][4];
#pragma unroll
    for (int u = 0; u < TM; u++)
#pragma unroll
        for (int v = 0; v < 4; v++) acc[u][v] = 0.f;

    for (int k0 = 0; k0 < K; k0 += 16) {
        // load A tile (BM x 16), store transposed As[k][m]
#pragma unroll
        for (int l = 0; l < BM / 16; l++) {
            int q = tid + l * 64;                 // 0 .. BM*4-1
            int row = q >> 2, c4 = q & 3;
            float4 f = *(const float4*)&A[(mo + row) * K + k0 + c4 * 4];
            As[(c4 * 4 + 0) * APAD + row] = f.x;
            As[(c4 * 4 + 1) * APAD + row] = f.y;
            As[(c4 * 4 + 2) * APAD + row] = f.z;
            As[(c4 * 4 + 3) * APAD + row] = f.w;
        }
        // load B tile (16 x 32)
        if (MODE != 3) {
#pragma unroll
            for (int l = 0; l < 2; l++) {
                int q = tid + l * 64;             // 0..127
                int r = q >> 3, c4 = q & 7;
                float4 f = *(const float4*)&Wb[(k0 + r) * ld + noff + c4 * 4];
                *(float4*)&Bs[r * 36 + c4 * 4] = f;
            }
        } else {
#pragma unroll
            for (int l = 0; l < 2; l++) {
                int q = tid + l * 64;             // 0..127
                int c = q >> 2, r4 = q & 3;
                float4 f = *(const float4*)&W[(no + c) * K + k0 + r4 * 4];
                Bs[(r4 * 4 + 0) * 36 + c] = f.x;
                Bs[(r4 * 4 + 1) * 36 + c] = f.y;
                Bs[(r4 * 4 + 2) * 36 + c] = f.z;
                Bs[(r4 * 4 + 3) * 36 + c] = f.w;
            }
        }
        __syncthreads();
#pragma unroll
        for (int kk = 0; kk < 16; kk++) {
            float a[TM];
            if (TM == 8) {
                float4 a0 = *(const float4*)&As[kk * APAD + ty * 8];
                float4 a1 = *(const float4*)&As[kk * APAD + ty * 8 + 4];
                a[0] = a0.x; a[1] = a0.y; a[2] = a0.z; a[3] = a0.w;
                a[4] = a1.x; a[5] = a1.y; a[6] = a1.z; a[7] = a1.w;
            } else {
                float4 a0 = *(const float4*)&As[kk * APAD + ty * 4];
                a[0] = a0.x; a[1] = a0.y; a[2] = a0.z; a[3] = a0.w;
            }
            float4 b4 = *(const float4*)&Bs[kk * 36 + tx * 4];
            float b[4] = {b4.x, b4.y, b4.z, b4.w};
#pragma unroll
            for (int u = 0; u < TM; u++)
#pragma unroll
                for (int v = 0; v < 4; v++) acc[u][v] += a[u] * b[v];
        }
        __syncthreads();
    }

    int col = no + tx * 4;
    // rotary angle factors (depend only on column) for MODE 2
    float inv0 = 0.f, inv1 = 0.f;
    bool do_rot = (MODE == 2) && (no < 1024);
    if (MODE == 2 && do_rot) {
        int d0 = col & 63;                        // even
        inv0 = expf(-((float)d0 / 64.f) * LN10000);
        inv1 = expf(-((float)(d0 + 2) / 64.f) * LN10000);
    }
#pragma unroll
    for (int u = 0; u < TM; u++) {
        int row = mo + ty * TM + u;
        float4 r;
        r.x = acc[u][0]; r.y = acc[u][1]; r.z = acc[u][2]; r.w = acc[u][3];
        if (MODE != 3) {
            r.x += bp[col]; r.y += bp[col + 1]; r.z += bp[col + 2]; r.w += bp[col + 3];
        }
        if (MODE == 1) {
            r.x = 0.5f * r.x * (1.f + erff(r.x * 0.70710678118654752f));
            r.y = 0.5f * r.y * (1.f + erff(r.y * 0.70710678118654752f));
            r.z = 0.5f * r.z * (1.f + erff(r.z * 0.70710678118654752f));
            r.w = 0.5f * r.w * (1.f + erff(r.w * 0.70710678118654752f));
        }
        if (MODE == 2 && do_rot) {
            float n = (float)(row & 127);
            float s0, c0, s1, c1;
            sincosf(n * inv0, &s0, &c0);
            sincosf(n * inv1, &s1, &c1);
            float x1 = r.x, x2 = r.y;
            r.x = x1 * c0 - x2 * s0;
            r.y = x2 * c0 + x1 * s0;
            x1 = r.z; x2 = r.w;
            r.z = x1 * c1 - x2 * s1;
            r.w = x2 * c1 + x1 * s1;
        }
        *(float4*)&C[row * N + col] = r;
    }
}

// ---------------- qw[b,i,h,c] = sum_d qrot[b,i,h*64+d] * w_ekv[c, h*64+d] ----------------
__global__ void qw_kernel(const float* __restrict__ qkv, const float* __restrict__ wekv,
                          float* __restrict__ qw) {
    __shared__ float qs[64];
    int bi = blockIdx.x, h = blockIdx.y;
    int tid = threadIdx.x;
    qs[tid] = qkv[bi * 1536 + h * 64 + tid];
    __syncthreads();
    float s = 0.f;
    const float* wr = wekv + tid * 512 + h * 64;
#pragma unroll 16
    for (int d = 0; d < 64; d++) s += qs[d] * wr[d];
    qw[(bi * 8 + h) * 64 + tid] = s;
}

// ---------------- sim_e[b,i,j,h] = sum_c qw[b,i,h,c] * e[b,i,j,c] ----------------
__global__ void sime_kernel(const float* __restrict__ e, const float* __restrict__ qw,
                            float* __restrict__ sime) {
    __shared__ float esm[128 * 65];
    __shared__ float qwsm[8 * 66];
    int bi = blockIdx.x, tid = threadIdx.x;
    const float* ep = e + (size_t)bi * 8192;
    for (int idx = tid; idx < 8192; idx += 256) {
        int j = idx >> 6, c = idx & 63;
        esm[j * 65 + c] = ep[idx];
    }
    for (int idx = tid; idx < 512; idx += 256) {
        int h = idx >> 6, c = idx & 63;
        qwsm[h * 66 + c] = qw[bi * 512 + idx];
    }
    __syncthreads();
    for (int idx = tid; idx < 1024; idx += 256) {
        int h = idx & 7, j = idx >> 3;
        float s = 0.f;
#pragma unroll 16
        for (int c = 0; c < 64; c++) s += qwsm[h * 66 + c] * esm[j * 65 + c];
        sime[bi * 1024 + idx] = s;
    }
}

// ---------------- attention core: per (b,h), chunk of 16 i ----------------
#define ATTN_SMEM ((128*65 + 128*64) * 4)
__global__ void attn_kernel(const float* __restrict__ qkv,
                            const float* __restrict__ sime,
                            float* __restrict__ att, float* __restrict__ aout) {
    extern __shared__ float dyn[];
    float* ksm = dyn;                 // 128*65
    float* vsm = dyn + 128 * 65;      // 128*64
    __shared__ float qs[64], attsm[128], psm[128], redm[4], reds[4];
    int bh = blockIdx.x;
    int b = bh >> 3, h = bh & 7;
    int i0 = blockIdx.y * 16;
    int tid = threadIdx.x, lane = tid & 31, w = tid >> 5;
    for (int idx = tid; idx < 8192; idx += 128) {
        int j = idx >> 6, d = idx & 63;
        ksm[j * 65 + d] = qkv[(b * 128 + j) * 1536 + 512 + h * 64 + d];
        vsm[j * 64 + d] = qkv[(b * 128 + j) * 1536 + 1024 + h * 64 + d];
    }
    __syncthreads();
    for (int ii = 0; ii < 16; ii++) {
        int i = i0 + ii;
        int bi = b * 128 + i;
        if (tid < 64) qs[tid] = qkv[bi * 1536 + h * 64 + tid];
        __syncthreads();
        int j = tid;
        float sim = sime[(bi * 128 + j) * 8 + h];
#pragma unroll 16
        for (int d = 0; d < 64; d++) sim += qs[d] * ksm[j * 65 + d];
        sim *= 0.125f;
        float m = sim;
#pragma unroll
        for (int o = 16; o; o >>= 1) m = fmaxf(m, __shfl_xor_sync(0xffffffffu, m, o));
        if (!lane) redm[w] = m;
        __syncthreads();
        m = fmaxf(fmaxf(redm[0], redm[1]), fmaxf(redm[2], redm[3]));
        float ex = expf(sim - m);
        float s = ex;
#pragma unroll
        for (int o = 16; o; o >>= 1) s += __shfl_xor_sync(0xffffffffu, s, o);
        if (!lane) reds[w] = s;
        __syncthreads();
        s = reds[0] + reds[1] + reds[2] + reds[3];
        float a = ex / s;
        attsm[tid] = a;
        att[(bi * 8 + h) * 128 + tid] = a;
        __syncthreads();
        int gg = tid >> 6, d = tid & 63;
        float acc = 0.f;
#pragma unroll 16
        for (int jj = 0; jj < 64; jj++) acc += attsm[gg * 64 + jj] * vsm[(gg * 64 + jj) * 64 + d];
        psm[tid] = acc;
        __syncthreads();
        if (tid < 64) aout[bi * 512 + h * 64 + tid] = psm[tid] + psm[64 + tid];
        __syncthreads();
    }
}

// ---------------- edge output: ae = att @ e ; aout += ae @ w_ekv + b_ekv ----------------
__global__ void edgeout_kernel(const float* __restrict__ e, const float* __restrict__ att,
                               const float* __restrict__ wekv, const float* __restrict__ bekv,
                               float* __restrict__ aout) {
    __shared__ float esm[128 * 65];
    __shared__ float asmem[8 * 128];
    __shared__ float aesm[8 * 66];
    int bi = blockIdx.x, tid = threadIdx.x;
    const float* ep = e + (size_t)bi * 8192;
    for (int idx = tid; idx < 8192; idx += 256) {
        int j = idx >> 6, c = idx & 63;
        esm[j * 65 + c] = ep[idx];
    }
    for (int idx = tid; idx < 1024; idx += 256) asmem[idx] = att[bi * 1024 + idx];
    __syncthreads();
    for (int idx = tid; idx < 512; idx += 256) {
        int h = idx >> 6, c = idx & 63;
        float s = 0.f;
#pragma unroll 16
        for (int j = 0; j < 128; j++) s += asmem[h * 128 + j] * esm[j * 65 + c];
        aesm[h * 66 + c] = s;
    }
    __syncthreads();
    for (int idx = tid; idx < 512; idx += 256) {
        int h = idx >> 6, d = idx & 63;
        float s = bekv[idx];
#pragma unroll 16
        for (int c = 0; c < 64; c++) s += aesm[h * 66 + c] * wekv[c * 512 + h * 64 + d];
        aout[bi * 512 + idx] += s;
    }
}

// ---------------- gated residual (in-place) + optional fused LayerNorm ----------------
__global__ void gate_ln_kernel(const float* __restrict__ x, float* __restrict__ nodes,
                               const float* __restrict__ gw,
                               const float* __restrict__ lng, const float* __restrict__ lnb,
                               float* __restrict__ lnout) {
    __shared__ float red[8];
    int row = blockIdx.x, t = threadIdx.x;
    float xv = x[row * 256 + t];
    float rv = nodes[row * 256 + t];
    float contrib = xv * gw[t] + rv * gw[256 + t] + (xv - rv) * gw[512 + t];
    float s = blockSum256(contrib, red);
    float gate = 1.f / (1.f + expf(-s));
    float nn = xv * gate + rv * (1.f - gate);
    nodes[row * 256 + t] = nn;
    if (lng) {
        float m = blockSum256(nn, red) * (1.f / 256.f);
        float d = nn - m;
        float var = blockSum256(d * d, red) * (1.f / 256.f);
        lnout[row * 256 + t] = d * rsqrtf(var + 1e-5f) * lng[t] + lnb[t];
    }
}

// ---------------- codebook squared norms ----------------
__global__ void cnorm_kernel(const float* __restrict__ cb, float* __restrict__ cn) {
    __shared__ float red[8];
    int k = blockIdx.x, t = threadIdx.x;
    float v = cb[k * 256 + t];
    float s = blockSum256(v * v, red);
    if (!t) cn[k] = s;
}

// ---------------- argmin + gather ----------------
__global__ void vq_kernel(const float* __restrict__ S, const float* __restrict__ cn,
                          const float* __restrict__ cb, const float* __restrict__ z,
                          float* __restrict__ out) {
    __shared__ float bv[256];
    __shared__ int bix[256];
    int r = blockIdx.x, t = threadIdx.x;
    float best = 1e30f; int bidx = 0;
    for (int k = t; k < 512; k += 256) {
        float v = cn[k] - 2.f * S[r * 512 + k];
        if (v < best) { best = v; bidx = k; }
    }
    bv[t] = best; bix[t] = bidx;
    __syncthreads();
    for (int s = 128; s; s >>= 1) {
        if (t < s) {
            float v2 = bv[t + s]; int i2 = bix[t + s];
            if (v2 < bv[t] || (v2 == bv[t] && i2 < bix[t])) { bv[t] = v2; bix[t] = i2; }
        }
        __syncthreads();
    }
    int k = bix[0];
    float zz = z[r * 256 + t];
    out[r * 256 + t] = zz + (cb[k * 256 + t] - zz);
}

// ---------------- host launch ----------------
extern "C" void kernel_launch(void* const* d_in, const int* in_sizes, int n_in,
                              void* d_out, int out_size) {
    const float* in_nodes = (const float*)d_in[0];
    const float* edges   = (const float*)d_in[1];
    const float* eg      = (const float*)d_in[2];
    const float* ebias   = (const float*)d_in[3];
    const float* ln1g    = (const float*)d_in[4];
    const float* ln1b    = (const float*)d_in[5];
    const float* wexp    = (const float*)d_in[6];
    const float* bexp    = (const float*)d_in[7];
    const float* wq      = (const float*)d_in[8];
    const float* bq      = (const float*)d_in[9];
    const float* wkv     = (const float*)d_in[10];
    const float* bkv     = (const float*)d_in[11];
    const float* wekv    = (const float*)d_in[12];
    const float* bekv    = (const float*)d_in[13];
    const float* wout    = (const float*)d_in[14];
    const float* bout    = (const float*)d_in[15];
    const float* g1      = (const float*)d_in[16];
    const float* ln2g    = (const float*)d_in[17];
    const float* ln2b    = (const float*)d_in[18];
    const float* wff1    = (const float*)d_in[19];
    const float* bff1    = (const float*)d_in[20];
    const float* wff2    = (const float*)d_in[21];
    const float* bff2    = (const float*)d_in[22];
    const float* g2      = (const float*)d_in[23];
    const float* cb      = (const float*)d_in[24];
    float* out = (float*)d_out;

    float* S;
    cudaGetSymbolAddress((void**)&S, g_scratch);
    float* E     = S + E_OFF;
    float* NODES = S + NODES_OFF;
    float* XN    = S + XN_OFF;
    float* XE    = S + XE_OFF;
    float* QKV   = S + QKV_OFF;
    float* QW    = S + QW_OFF;
    float* SIME  = S + SIME_OFF;
    float* ATT   = S + ATT_OFF;
    float* AOUT  = S + AOUT_OFF;
    float* OUT2  = S + OUT2_OFF;
    float* H1    = S + H1_OFF;
    float* H2    = S + H2_OFF;
    float* CN    = S + CN_OFF;

    cudaFuncSetAttribute(attn_kernel, cudaFuncAttributeMaxDynamicSharedMemorySize, ATTN_SMEM);

    cudaMemcpyAsync(NODES, in_nodes, (size_t)ROWS * 256 * sizeof(float),
                    cudaMemcpyDeviceToDevice);

    edge_ln_kernel<<<512, 256>>>(edges, eg, ebias, E);
    ln_rows_kernel<<<512, 256>>>(NODES, ln1g, ln1b, XN);

    for (int l = 0; l < 2; l++) {
        // XE = XN @ wexp + bexp          (512x512, K=256)
        gemm_kernel<0, 8><<<dim3(16, 8), 64>>>(XN, wexp + l * 131072, nullptr,
                                               bexp + l * 512, nullptr, XE, 512, 256, 512, 0);
        // QKV = XE @ [wq | wkv] + bias, rotary on Q,K   (512x1536, K=512)
        gemm_kernel<2, 8><<<dim3(48, 8), 64>>>(XE, wq + l * 262144, wkv + l * 524288,
                                               bq + l * 512, bkv + l * 1024, QKV,
                                               1536, 512, 512, 1024);
        qw_kernel<<<dim3(512, 8), 64>>>(QKV, wekv + l * 32768, QW);
        sime_kernel<<<512, 256>>>(E, QW, SIME);
        attn_kernel<<<dim3(32, 8), 128, ATTN_SMEM>>>(QKV, SIME, ATT, AOUT);
        edgeout_kernel<<<512, 256>>>(E, ATT, wekv + l * 32768, bekv + l * 512, AOUT);
        // OUT2 = AOUT @ wout + bout      (512x256, K=512)
        gemm_kernel<0, 4><<<dim3(8, 16), 64>>>(AOUT, wout + l * 131072, nullptr,
                                               bout + l * 256, nullptr, OUT2, 256, 512, 256, 0);
        gate_ln_kernel<<<512, 256>>>(OUT2, NODES, g1 + l * 768,
                                     ln2g + l * 256, ln2b + l * 256, XN);
        // H1 = gelu(XN @ wff1 + bff1)    (512x1024, K=256)
        gemm_kernel<1, 8><<<dim3(32, 8), 64>>>(XN, wff1 + l * 262144, nullptr,
                                               bff1 + l * 1024, nullptr, H1, 1024, 256, 1024, 0);
        // H2 = H1 @ wff2 + bff2          (512x256, K=1024)
        gemm_kernel<0, 4><<<dim3(8, 16), 64>>>(H1, wff2 + l * 262144, nullptr,
                                               bff2 + l * 256, nullptr, H2, 256, 1024, 256, 0);
        if (l == 0) {
            gate_ln_kernel<<<512, 256>>>(H2, NODES, g2 + l * 768,
                                         ln1g + 256, ln1b + 256, XN);
        } else {
            gate_ln_kernel<<<512, 256>>>(H2, NODES, g2 + l * 768,
                                         nullptr, nullptr, nullptr);
        }
    }

    cnorm_kernel<<<512, 256>>>(cb, CN);
    // VQ scores: S = NODES @ cb^T        (512x512, K=256)
    gemm_kernel<3, 8><<<dim3(16, 8), 64>>>(NODES, cb, nullptr, nullptr, nullptr,
                                           XE, 512, 256, 0, 0);
    vq_kernel<<<512, 256>>>(XE, CN, cb, NODES, out);
}

// round 10
// speedup vs baseline: 1.0945x; 1.0926x over previous
#include <cuda_runtime.h>
#include <cuda_bf16.h>
#include <math.h>

// Problem constants
#define BB   4
#define NN   128
#define DIM  256
#define HH   8
#define DHH  64
#define EE   64
#define INNER 512
#define ROWS 512          // B*N
#define LN10000 9.210340371976184f

// ---------------- scratch (one big static device buffer) ----------------
#define E_OFF     0            // 4*128*128*64 = 4194304  (edge LN result, (b,i,j,c))
#define NODES_OFF 4194304      // 131072
#define XN_OFF    4325376      // 131072
#define XE_OFF    4456448      // 262144 (also VQ scores 512x512)
#define QKV_OFF   4718592      // 512*1536 = 786432  [Q | K | V] rotated
#define QW_OFF    5505024      // 262144  (b,i,h,c)
#define SIME_OFF  5767168      // 524288  (b,i,j,h)
#define ATT_OFF   6291456      // 524288  (b,i,h,j)
#define AOUT_OFF  6815744      // 262144
#define OUT2_OFF  7077888      // 131072
#define H1_OFF    7208960      // 524288
#define H2_OFF    7733248      // 131072
#define CN_OFF    7864320      // 512
#define SCRATCH_FLOATS 7864832

__device__ float g_scratch[SCRATCH_FLOATS];

// ---------------- reductions ----------------
__device__ __forceinline__ float blockSum256(float v, float* red8) {
    int lane = threadIdx.x & 31, w = threadIdx.x >> 5;
#pragma unroll
    for (int o = 16; o; o >>= 1) v += __shfl_xor_sync(0xffffffffu, v, o);
    if (!lane) red8[w] = v;
    __syncthreads();
    float t = (threadIdx.x < 8) ? red8[threadIdx.x] : 0.f;
    if (w == 0) {
#pragma unroll
        for (int o = 4; o; o >>= 1) t += __shfl_xor_sync(0xffffffffu, t, o);
        if (!lane) red8[0] = t;
    }
    __syncthreads();
    v = red8[0];
    __syncthreads();
    return v;
}

__device__ __forceinline__ unsigned f2tf(float x) {
    unsigned r;
    asm("cvt.rna.tf32.f32 %0, %1;" : "=r"(r) : "f"(x));
    return r;
}

// ---------------- edge LayerNorm: edges (B,E,N,N) -> e (B,N,N,E) ----------------
__global__ void edge_ln_kernel(const float* __restrict__ edges,
                               const float* __restrict__ g, const float* __restrict__ b,
                               float* __restrict__ e) {
    __shared__ float s[64 * 129];
    __shared__ float mn[128], rs[128];
    int bi = blockIdx.x;              // b*128 + i
    int bidx = bi >> 7, i = bi & 127;
    int tid = threadIdx.x;
    for (int idx = tid; idx < 8192; idx += 256) {
        int c = idx >> 7, j = idx & 127;
        s[c * 129 + j] = edges[((bidx * 64 + c) * 128 + i) * 128 + j];
    }
    __syncthreads();
    if (tid < 128) {
        int j = tid;
        float sum = 0.f;
#pragma unroll 16
        for (int c = 0; c < 64; c++) sum += s[c * 129 + j];
        float m = sum * (1.f / 64.f);
        float var = 0.f;
#pragma unroll 16
        for (int c = 0; c < 64; c++) { float d = s[c * 129 + j] - m; var += d * d; }
        var *= (1.f / 64.f);
        mn[j] = m;
        rs[j] = rsqrtf(var + 1e-5f);
    }
    __syncthreads();
    float* ep = e + (size_t)bi * 8192;
    for (int idx = tid; idx < 8192; idx += 256) {
        int j = idx >> 6, c = idx & 63;
        ep[idx] = (s[c * 129 + j] - mn[j]) * rs[j] * g[c] + b[c];
    }
}

// ---------------- row LayerNorm over 256 ----------------
__global__ void ln_rows_kernel(const float* __restrict__ in,
                               const float* __restrict__ g, const float* __restrict__ b,
                               float* __restrict__ out) {
    __shared__ float red[8];
    int row = blockIdx.x, t = threadIdx.x;
    float x = in[row * 256 + t];
    float m = blockSum256(x, red) * (1.f / 256.f);
    float d = x - m;
    float var = blockSum256(d * d, red) * (1.f / 256.f);
    out[row * 256 + t] = d * rsqrtf(var + 1e-5f) * g[t] + b[t];
}

// ================= tf32 tensor-core GEMM =================
// 128 threads = 4 warps (2x2), BM=64, BN=32, BK=32. Warp tile 32x16.
// MODE 0: C = A@W + bias
// MODE 1: C = gelu(A@W + bias)
// MODE 2: QKV: cols [0,512)->W(ldw), [512,1536)->W2(ldw2); rotary on cols<1024
template<int MODE>
__global__ __launch_bounds__(128) void gemm_tc(
        const float* __restrict__ A, const float* __restrict__ W,
        const float* __restrict__ W2,
        const float* __restrict__ bias, const float* __restrict__ bias2,
        float* __restrict__ C, int N, int K, int ldw, int ldw2) {
    __shared__ __align__(16) unsigned As[64 * 36];
    __shared__ __align__(16) unsigned Bs[32 * 36];
    int tid = threadIdx.x;
    int lane = tid & 31, wid = tid >> 5;
    int wm = wid >> 1, wn = wid & 1;
    int g = lane >> 2, tig = lane & 3;
    int mo = blockIdx.y * 64, no = blockIdx.x * 32;

    const float* Wb = W;
    const float* bp = bias;
    int ld = ldw, noff = no;
    if (MODE == 2 && no >= 512) { Wb = W2; ld = ldw2; noff = no - 512; bp = bias2 - 512; }

    float acc[2][2][4];
#pragma unroll
    for (int mt = 0; mt < 2; mt++)
#pragma unroll
        for (int nt = 0; nt < 2; nt++)
#pragma unroll
            for (int v = 0; v < 4; v++) acc[mt][nt][v] = 0.f;

    for (int k0 = 0; k0 < K; k0 += 32) {
        // A tile (64 x 32) -> As[m][k], tf32-converted
#pragma unroll
        for (int i = 0; i < 4; i++) {
            int q = tid + i * 128;            // 0..511
            int row = q >> 3, c4 = q & 7;
            float4 f = *(const float4*)&A[(mo + row) * K + k0 + c4 * 4];
            unsigned* p = &As[row * 36 + c4 * 4];
            p[0] = f2tf(f.x); p[1] = f2tf(f.y); p[2] = f2tf(f.z); p[3] = f2tf(f.w);
        }
        // B tile (32k x 32n) -> Bs[n][k]
#pragma unroll
        for (int i = 0; i < 2; i++) {
            int q = tid + i * 128;            // 0..255
            int k = q >> 3, n4 = q & 7;
            float4 f = *(const float4*)&Wb[(k0 + k) * ld + noff + n4 * 4];
            Bs[(n4 * 4 + 0) * 36 + k] = f2tf(f.x);
            Bs[(n4 * 4 + 1) * 36 + k] = f2tf(f.y);
            Bs[(n4 * 4 + 2) * 36 + k] = f2tf(f.z);
            Bs[(n4 * 4 + 3) * 36 + k] = f2tf(f.w);
        }
        __syncthreads();
#pragma unroll
        for (int ks = 0; ks < 4; ks++) {
            unsigned a[2][4], b[2][2];
#pragma unroll
            for (int mt = 0; mt < 2; mt++) {
                int rb = wm * 32 + mt * 16;
                a[mt][0] = As[(rb + g) * 36 + ks * 8 + tig];
                a[mt][1] = As[(rb + g + 8) * 36 + ks * 8 + tig];
                a[mt][2] = As[(rb + g) * 36 + ks * 8 + tig + 4];
                a[mt][3] = As[(rb + g + 8) * 36 + ks * 8 + tig + 4];
            }
#pragma unroll
            for (int nt = 0; nt < 2; nt++) {
                int cb2 = wn * 16 + nt * 8;
                b[nt][0] = Bs[(cb2 + g) * 36 + ks * 8 + tig];
                b[nt][1] = Bs[(cb2 + g) * 36 + ks * 8 + tig + 4];
            }
#pragma unroll
            for (int mt = 0; mt < 2; mt++)
#pragma unroll
                for (int nt = 0; nt < 2; nt++) {
                    asm volatile(
                        "mma.sync.aligned.m16n8k8.row.col.f32.tf32.tf32.f32 "
                        "{%0,%1,%2,%3}, {%4,%5,%6,%7}, {%8,%9}, {%0,%1,%2,%3};"
                        : "+f"(acc[mt][nt][0]), "+f"(acc[mt][nt][1]),
                          "+f"(acc[mt][nt][2]), "+f"(acc[mt][nt][3])
                        : "r"(a[mt][0]), "r"(a[mt][1]), "r"(a[mt][2]), "r"(a[mt][3]),
                          "r"(b[nt][0]), "r"(b[nt][1]));
                }
        }
        __syncthreads();
    }

    // epilogue
#pragma unroll
    for (int mt = 0; mt < 2; mt++) {
#pragma unroll
        for (int nt = 0; nt < 2; nt++) {
            int row0 = mo + wm * 32 + mt * 16 + g;
            int col0 = no + wn * 16 + nt * 8 + 2 * tig;
            float v0 = acc[mt][nt][0], v1 = acc[mt][nt][1];
            float v2 = acc[mt][nt][2], v3 = acc[mt][nt][3];
            v0 += bp[col0]; v1 += bp[col0 + 1];
            v2 += bp[col0]; v3 += bp[col0 + 1];
            if (MODE == 1) {
                v0 = 0.5f * v0 * (1.f + erff(v0 * 0.70710678118654752f));
                v1 = 0.5f * v1 * (1.f + erff(v1 * 0.70710678118654752f));
                v2 = 0.5f * v2 * (1.f + erff(v2 * 0.70710678118654752f));
                v3 = 0.5f * v3 * (1.f + erff(v3 * 0.70710678118654752f));
            }
            if (MODE == 2 && no < 1024) {
                int d0 = col0 & 63;
                float inv = expf(-((float)d0 / 64.f) * LN10000);
                float s0, c0, s1, c1;
                sincosf((float)(row0 & 127) * inv, &s0, &c0);
                sincosf((float)((row0 + 8) & 127) * inv, &s1, &c1);
                float x1 = v0, x2 = v1;
                v0 = x1 * c0 - x2 * s0;
                v1 = x2 * c0 + x1 * s0;
                x1 = v2; x2 = v3;
                v2 = x1 * c1 - x2 * s1;
                v3 = x2 * c1 + x1 * s1;
            }
            C[row0 * N + col0] = v0;
            C[row0 * N + col0 + 1] = v1;
            C[(row0 + 8) * N + col0] = v2;
            C[(row0 + 8) * N + col0 + 1] = v3;
        }
    }
}

// ---------------- fp32 SIMT GEMM (kept for VQ scores: C = A @ W^T) ----------------
__global__ __launch_bounds__(64) void gemm_vq_kernel(
        const float* __restrict__ A, const float* __restrict__ W,
        float* __restrict__ C, int N, int K) {
    constexpr int BM = 64;
    constexpr int APAD = BM + 4;
    __shared__ __align__(16) float As[16 * APAD];
    __shared__ __align__(16) float Bs[16 * 36];
    int tid = threadIdx.x;
    int tx = tid & 7, ty = tid >> 3;
    int mo = blockIdx.y * BM, no = blockIdx.x * 32;
    float acc[8][4] = {};
    for (int k0 = 0; k0 < K; k0 += 16) {
#pragma unroll
        for (int l = 0; l < 4; l++) {
            int q = tid + l * 64;
            int row = q >> 2, c4 = q & 3;
            float4 f = *(const float4*)&A[(mo + row) * K + k0 + c4 * 4];
            As[(c4 * 4 + 0) * APAD + row] = f.x;
            As[(c4 * 4 + 1) * APAD + row] = f.y;
            As[(c4 * 4 + 2) * APAD + row] = f.z;
            As[(c4 * 4 + 3) * APAD + row] = f.w;
        }
#pragma unroll
        for (int l = 0; l < 2; l++) {
            int q = tid + l * 64;
            int c = q >> 2, r4 = q & 3;
            float4 f = *(const float4*)&W[(no + c) * K + k0 + r4 * 4];
            Bs[(r4 * 4 + 0) * 36 + c] = f.x;
            Bs[(r4 * 4 + 1) * 36 + c] = f.y;
            Bs[(r4 * 4 + 2) * 36 + c] = f.z;
            Bs[(r4 * 4 + 3) * 36 + c] = f.w;
        }
        __syncthreads();
#pragma unroll
        for (int kk = 0; kk < 16; kk++) {
            float a[8];
            float4 a0 = *(const float4*)&As[kk * APAD + ty * 8];
            float4 a1 = *(const float4*)&As[kk * APAD + ty * 8 + 4];
            a[0] = a0.x; a[1] = a0.y; a[2] = a0.z; a[3] = a0.w;
            a[4] = a1.x; a[5] = a1.y; a[6] = a1.z; a[7] = a1.w;
            float4 b4 = *(const float4*)&Bs[kk * 36 + tx * 4];
            float b[4] = {b4.x, b4.y, b4.z, b4.w};
#pragma unroll
            for (int u = 0; u < 8; u++)
#pragma unroll
                for (int v = 0; v < 4; v++) acc[u][v] += a[u] * b[v];
        }
        __syncthreads();
    }
#pragma unroll
    for (int u = 0; u < 8; u++) {
        int row = mo + ty * 8 + u;
        float4 r;
        r.x = acc[u][0]; r.y = acc[u][1]; r.z = acc[u][2]; r.w = acc[u][3];
        *(float4*)&C[row * N + no + tx * 4] = r;
    }
}

// ---------------- qw[b,i,h,c] = sum_d qrot[b,i,h*64+d] * w_ekv[c, h*64+d] ----------------
__global__ void qw_kernel(const float* __restrict__ qkv, const float* __restrict__ wekv,
                          float* __restrict__ qw) {
    __shared__ float qs[64];
    int bi = blockIdx.x, h = blockIdx.y;
    int tid = threadIdx.x;
    qs[tid] = qkv[bi * 1536 + h * 64 + tid];
    __syncthreads();
    float s = 0.f;
    const float* wr = wekv + tid * 512 + h * 64;
#pragma unroll 16
    for (int d = 0; d < 64; d++) s += qs[d] * wr[d];
    qw[(bi * 8 + h) * 64 + tid] = s;
}

// ---------------- sim_e[b,i,j,h] = sum_c qw[b,i,h,c] * e[b,i,j,c] ----------------
__global__ void sime_kernel(const float* __restrict__ e, const float* __restrict__ qw,
                            float* __restrict__ sime) {
    __shared__ float esm[128 * 65];
    __shared__ float qwsm[8 * 66];
    int bi = blockIdx.x, tid = threadIdx.x;
    const float* ep = e + (size_t)bi * 8192;
    for (int idx = tid; idx < 8192; idx += 256) {
        int j = idx >> 6, c = idx & 63;
        esm[j * 65 + c] = ep[idx];
    }
    for (int idx = tid; idx < 512; idx += 256) {
        int h = idx >> 6, c = idx & 63;
        qwsm[h * 66 + c] = qw[bi * 512 + idx];
    }
    __syncthreads();
    for (int idx = tid; idx < 1024; idx += 256) {
        int h = idx & 7, j = idx >> 3;
        float s = 0.f;
#pragma unroll 16
        for (int c = 0; c < 64; c++) s += qwsm[h * 66 + c] * esm[j * 65 + c];
        sime[bi * 1024 + idx] = s;
    }
}

// ---------------- attention core: per (b,h), chunk of 16 i ----------------
#define ATTN_SMEM ((128*65 + 128*64) * 4)
__global__ void attn_kernel(const float* __restrict__ qkv,
                            const float* __restrict__ sime,
                            float* __restrict__ att, float* __restrict__ aout) {
    extern __shared__ float dyn[];
    float* ksm = dyn;                 // 128*65
    float* vsm = dyn + 128 * 65;      // 128*64
    __shared__ float qs[64], attsm[128], psm[128], redm[4], reds[4];
    int bh = blockIdx.x;
    int b = bh >> 3, h = bh & 7;
    int i0 = blockIdx.y * 16;
    int tid = threadIdx.x, lane = tid & 31, w = tid >> 5;
    for (int idx = tid; idx < 8192; idx += 128) {
        int j = idx >> 6, d = idx & 63;
        ksm[j * 65 + d] = qkv[(b * 128 + j) * 1536 + 512 + h * 64 + d];
        vsm[j * 64 + d] = qkv[(b * 128 + j) * 1536 + 1024 + h * 64 + d];
    }
    __syncthreads();
    for (int ii = 0; ii < 16; ii++) {
        int i = i0 + ii;
        int bi = b * 128 + i;
        if (tid < 64) qs[tid] = qkv[bi * 1536 + h * 64 + tid];
        __syncthreads();
        int j = tid;
        float sim = sime[(bi * 128 + j) * 8 + h];
#pragma unroll 16
        for (int d = 0; d < 64; d++) sim += qs[d] * ksm[j * 65 + d];
        sim *= 0.125f;
        float m = sim;
#pragma unroll
        for (int o = 16; o; o >>= 1) m = fmaxf(m, __shfl_xor_sync(0xffffffffu, m, o));
        if (!lane) redm[w] = m;
        __syncthreads();
        m = fmaxf(fmaxf(redm[0], redm[1]), fmaxf(redm[2], redm[3]));
        float ex = expf(sim - m);
        float s = ex;
#pragma unroll
        for (int o = 16; o; o >>= 1) s += __shfl_xor_sync(0xffffffffu, s, o);
        if (!lane) reds[w] = s;
        __syncthreads();
        s = reds[0] + reds[1] + reds[2] + reds[3];
        float a = ex / s;
        attsm[tid] = a;
        att[(bi * 8 + h) * 128 + tid] = a;
        __syncthreads();
        int gg = tid >> 6, d = tid & 63;
        float acc = 0.f;
#pragma unroll 16
        for (int jj = 0; jj < 64; jj++) acc += attsm[gg * 64 + jj] * vsm[(gg * 64 + jj) * 64 + d];
        psm[tid] = acc;
        __syncthreads();
        if (tid < 64) aout[bi * 512 + h * 64 + tid] = psm[tid] + psm[64 + tid];
        __syncthreads();
    }
}

// ---------------- edge output: ae = att @ e ; aout += ae @ w_ekv + b_ekv ----------------
__global__ void edgeout_kernel(const float* __restrict__ e, const float* __restrict__ att,
                               const float* __restrict__ wekv, const float* __restrict__ bekv,
                               float* __restrict__ aout) {
    __shared__ float esm[128 * 65];
    __shared__ float asmem[8 * 128];
    __shared__ float aesm[8 * 66];
    int bi = blockIdx.x, tid = threadIdx.x;
    const float* ep = e + (size_t)bi * 8192;
    for (int idx = tid; idx < 8192; idx += 256) {
        int j = idx >> 6, c = idx & 63;
        esm[j * 65 + c] = ep[idx];
    }
    for (int idx = tid; idx < 1024; idx += 256) asmem[idx] = att[bi * 1024 + idx];
    __syncthreads();
    for (int idx = tid; idx < 512; idx += 256) {
        int h = idx >> 6, c = idx & 63;
        float s = 0.f;
#pragma unroll 16
        for (int j = 0; j < 128; j++) s += asmem[h * 128 + j] * esm[j * 65 + c];
        aesm[h * 66 + c] = s;
    }
    __syncthreads();
    for (int idx = tid; idx < 512; idx += 256) {
        int h = idx >> 6, d = idx & 63;
        float s = bekv[idx];
#pragma unroll 16
        for (int c = 0; c < 64; c++) s += aesm[h * 66 + c] * wekv[c * 512 + h * 64 + d];
        aout[bi * 512 + idx] += s;
    }
}

// ---------------- gated residual (in-place) + optional fused LayerNorm ----------------
__global__ void gate_ln_kernel(const float* __restrict__ x, float* __restrict__ nodes,
                               const float* __restrict__ gw,
                               const float* __restrict__ lng, const float* __restrict__ lnb,
                               float* __restrict__ lnout) {
    __shared__ float red[8];
    int row = blockIdx.x, t = threadIdx.x;
    float xv = x[row * 256 + t];
    float rv = nodes[row * 256 + t];
    float contrib = xv * gw[t] + rv * gw[256 + t] + (xv - rv) * gw[512 + t];
    float s = blockSum256(contrib, red);
    float gate = 1.f / (1.f + expf(-s));
    float nn = xv * gate + rv * (1.f - gate);
    nodes[row * 256 + t] = nn;
    if (lng) {
        float m = blockSum256(nn, red) * (1.f / 256.f);
        float d = nn - m;
        float var = blockSum256(d * d, red) * (1.f / 256.f);
        lnout[row * 256 + t] = d * rsqrtf(var + 1e-5f) * lng[t] + lnb[t];
    }
}

// ---------------- codebook squared norms ----------------
__global__ void cnorm_kernel(const float* __restrict__ cb, float* __restrict__ cn) {
    __shared__ float red[8];
    int k = blockIdx.x, t = threadIdx.x;
    float v = cb[k * 256 + t];
    float s = blockSum256(v * v, red);
    if (!t) cn[k] = s;
}

// ---------------- argmin + gather ----------------
__global__ void vq_kernel(const float* __restrict__ S, const float* __restrict__ cn,
                          const float* __restrict__ cb, const float* __restrict__ z,
                          float* __restrict__ out) {
    __shared__ float bv[256];
    __shared__ int bix[256];
    int r = blockIdx.x, t = threadIdx.x;
    float best = 1e30f; int bidx = 0;
    for (int k = t; k < 512; k += 256) {
        float v = cn[k] - 2.f * S[r * 512 + k];
        if (v < best) { best = v; bidx = k; }
    }
    bv[t] = best; bix[t] = bidx;
    __syncthreads();
    for (int s = 128; s; s >>= 1) {
        if (t < s) {
            float v2 = bv[t + s]; int i2 = bix[t + s];
            if (v2 < bv[t] || (v2 == bv[t] && i2 < bix[t])) { bv[t] = v2; bix[t] = i2; }
        }
        __syncthreads();
    }
    int k = bix[0];
    float zz = z[r * 256 + t];
    out[r * 256 + t] = zz + (cb[k * 256 + t] - zz);
}

// ---------------- host launch ----------------
extern "C" void kernel_launch(void* const* d_in, const int* in_sizes, int n_in,
                              void* d_out, int out_size) {
    const float* in_nodes = (const float*)d_in[0];
    const float* edges   = (const float*)d_in[1];
    const float* eg      = (const float*)d_in[2];
    const float* ebias   = (const float*)d_in[3];
    const float* ln1g    = (const float*)d_in[4];
    const float* ln1b    = (const float*)d_in[5];
    const float* wexp    = (const float*)d_in[6];
    const float* bexp    = (const float*)d_in[7];
    const float* wq      = (const float*)d_in[8];
    const float* bq      = (const float*)d_in[9];
    const float* wkv     = (const float*)d_in[10];
    const float* bkv     = (const float*)d_in[11];
    const float* wekv    = (const float*)d_in[12];
    const float* bekv    = (const float*)d_in[13];
    const float* wout    = (const float*)d_in[14];
    const float* bout    = (const float*)d_in[15];
    const float* g1      = (const float*)d_in[16];
    const float* ln2g    = (const float*)d_in[17];
    const float* ln2b    = (const float*)d_in[18];
    const float* wff1    = (const float*)d_in[19];
    const float* bff1    = (const float*)d_in[20];
    const float* wff2    = (const float*)d_in[21];
    const float* bff2    = (const float*)d_in[22];
    const float* g2      = (const float*)d_in[23];
    const float* cb      = (const float*)d_in[24];
    float* out = (float*)d_out;

    float* S;
    cudaGetSymbolAddress((void**)&S, g_scratch);
    float* E     = S + E_OFF;
    float* NODES = S + NODES_OFF;
    float* XN    = S + XN_OFF;
    float* XE    = S + XE_OFF;
    float* QKV   = S + QKV_OFF;
    float* QW    = S + QW_OFF;
    float* SIME  = S + SIME_OFF;
    float* ATT   = S + ATT_OFF;
    float* AOUT  = S + AOUT_OFF;
    float* OUT2  = S + OUT2_OFF;
    float* H1    = S + H1_OFF;
    float* H2    = S + H2_OFF;
    float* CN    = S + CN_OFF;

    cudaFuncSetAttribute(attn_kernel, cudaFuncAttributeMaxDynamicSharedMemorySize, ATTN_SMEM);

    cudaMemcpyAsync(NODES, in_nodes, (size_t)ROWS * 256 * sizeof(float),
                    cudaMemcpyDeviceToDevice);

    edge_ln_kernel<<<512, 256>>>(edges, eg, ebias, E);
    ln_rows_kernel<<<512, 256>>>(NODES, ln1g, ln1b, XN);

    for (int l = 0; l < 2; l++) {
        // XE = XN @ wexp + bexp          (512x512, K=256)
        gemm_tc<0><<<dim3(16, 8), 128>>>(XN, wexp + l * 131072, nullptr,
                                         bexp + l * 512, nullptr, XE, 512, 256, 512, 0);
        // QKV = XE @ [wq | wkv] + bias, rotary on Q,K   (512x1536, K=512)
        gemm_tc<2><<<dim3(48, 8), 128>>>(XE, wq + l * 262144, wkv + l * 524288,
                                         bq + l * 512, bkv + l * 1024, QKV,
                                         1536, 512, 512, 1024);
        qw_kernel<<<dim3(512, 8), 64>>>(QKV, wekv + l * 32768, QW);
        sime_kernel<<<512, 256>>>(E, QW, SIME);
        attn_kernel<<<dim3(32, 8), 128, ATTN_SMEM>>>(QKV, SIME, ATT, AOUT);
        edgeout_kernel<<<512, 256>>>(E, ATT, wekv + l * 32768, bekv + l * 512, AOUT);
        // OUT2 = AOUT @ wout + bout      (512x256, K=512)
        gemm_tc<0><<<dim3(8, 8), 128>>>(AOUT, wout + l * 131072, nullptr,
                                        bout + l * 256, nullptr, OUT2, 256, 512, 256, 0);
        gate_ln_kernel<<<512, 256>>>(OUT2, NODES, g1 + l * 768,
                                     ln2g + l * 256, ln2b + l * 256, XN);
        // H1 = gelu(XN @ wff1 + bff1)    (512x1024, K=256)
        gemm_tc<1><<<dim3(32, 8), 128>>>(XN, wff1 + l * 262144, nullptr,
                                         bff1 + l * 1024, nullptr, H1, 1024, 256, 1024, 0);
        // H2 = H1 @ wff2 + bff2          (512x256, K=1024)
        gemm_tc<0><<<dim3(8, 8), 128>>>(H1, wff2 + l * 262144, nullptr,
                                        bff2 + l * 256, nullptr, H2, 256, 1024, 256, 0);
        if (l == 0) {
            gate_ln_kernel<<<512, 256>>>(H2, NODES, g2 + l * 768,
                                         ln1g + 256, ln1b + 256, XN);
        } else {
            gate_ln_kernel<<<512, 256>>>(H2, NODES, g2 + l * 768,
                                         nullptr, nullptr, nullptr);
        }
    }

    cnorm_kernel<<<512, 256>>>(cb, CN);
    // VQ scores: S = NODES @ cb^T (fp32 SIMT — argmin precision)  (512x512, K=256)
    gemm_vq_kernel<<<dim3(16, 8), 64>>>(NODES, cb, XE, 512, 256);
    vq_kernel<<<512, 256>>>(XE, CN, cb, NODES, out);
}

// round 11
// speedup vs baseline: 1.3586x; 1.2413x over previous
#include <cuda_runtime.h>
#include <cuda_bf16.h>
#include <math.h>

// Problem constants
#define BB   4
#define NN   128
#define DIM  256
#define HH   8
#define DHH  64
#define EE   64
#define INNER 512
#define ROWS 512          // B*N
#define LN10000 9.210340371976184f

// ---------------- scratch (one big static device buffer) ----------------
#define E_OFF     0            // 4*128*128*64 = 4194304  (edge LN result, (b,i,j,c))
#define NODES_OFF 4194304      // 131072
#define XN_OFF    4325376      // 131072
#define XE_OFF    4456448      // 262144 (also VQ scores 512x512)
#define QKV_OFF   4718592      // 512*1536 = 786432  [Q | K | V] rotated
#define SIME_OFF  5767168      // 524288  (b,i,j,h)
#define ATT_OFF   6291456      // 524288  (b,i,h,j)
#define AOUT_OFF  6815744      // 262144
#define OUT2_OFF  7077888      // 131072
#define H1_OFF    7208960      // 524288
#define H2_OFF    7733248      // 131072
#define CN_OFF    7864320      // 512
#define SCRATCH_FLOATS 7864832

__device__ float g_scratch[SCRATCH_FLOATS];

// ---------------- reductions ----------------
__device__ __forceinline__ float blockSum256(float v, float* red8) {
    int lane = threadIdx.x & 31, w = threadIdx.x >> 5;
#pragma unroll
    for (int o = 16; o; o >>= 1) v += __shfl_xor_sync(0xffffffffu, v, o);
    if (!lane) red8[w] = v;
    __syncthreads();
    float t = (threadIdx.x < 8) ? red8[threadIdx.x] : 0.f;
    if (w == 0) {
#pragma unroll
        for (int o = 4; o; o >>= 1) t += __shfl_xor_sync(0xffffffffu, t, o);
        if (!lane) red8[0] = t;
    }
    __syncthreads();
    v = red8[0];
    __syncthreads();
    return v;
}

__device__ __forceinline__ unsigned f2tf(float x) {
    unsigned r;
    asm("cvt.rna.tf32.f32 %0, %1;" : "=r"(r) : "f"(x));
    return r;
}

__device__ __forceinline__ void cpasync16(void* smem_dst, const void* gsrc) {
    unsigned s = (unsigned)__cvta_generic_to_shared(smem_dst);
    asm volatile("cp.async.cg.shared.global [%0], [%1], 16;\n" :: "r"(s), "l"(gsrc));
}
#define CP_COMMIT() asm volatile("cp.async.commit_group;\n" ::: "memory")
#define CP_WAIT1()  asm volatile("cp.async.wait_group 1;\n" ::: "memory")
#define CP_WAIT0()  asm volatile("cp.async.wait_group 0;\n" ::: "memory")

// ---------------- edge LayerNorm: edges (B,E,N,N) -> e (B,N,N,E) ----------------
__global__ void edge_ln_kernel(const float* __restrict__ edges,
                               const float* __restrict__ g, const float* __restrict__ b,
                               float* __restrict__ e) {
    __shared__ float s[64 * 129];
    __shared__ float mn[128], rs[128];
    int bi = blockIdx.x;              // b*128 + i
    int bidx = bi >> 7, i = bi & 127;
    int tid = threadIdx.x;
    for (int idx = tid; idx < 8192; idx += 256) {
        int c = idx >> 7, j = idx & 127;
        s[c * 129 + j] = edges[((bidx * 64 + c) * 128 + i) * 128 + j];
    }
    __syncthreads();
    if (tid < 128) {
        int j = tid;
        float sum = 0.f;
#pragma unroll 16
        for (int c = 0; c < 64; c++) sum += s[c * 129 + j];
        float m = sum * (1.f / 64.f);
        float var = 0.f;
#pragma unroll 16
        for (int c = 0; c < 64; c++) { float d = s[c * 129 + j] - m; var += d * d; }
        var *= (1.f / 64.f);
        mn[j] = m;
        rs[j] = rsqrtf(var + 1e-5f);
    }
    __syncthreads();
    float* ep = e + (size_t)bi * 8192;
    for (int idx = tid; idx < 8192; idx += 256) {
        int j = idx >> 6, c = idx & 63;
        ep[idx] = (s[c * 129 + j] - mn[j]) * rs[j] * g[c] + b[c];
    }
}

// ---------------- row LayerNorm over 256 ----------------
__global__ void ln_rows_kernel(const float* __restrict__ in,
                               const float* __restrict__ g, const float* __restrict__ b,
                               float* __restrict__ out) {
    __shared__ float red[8];
    int row = blockIdx.x, t = threadIdx.x;
    float x = in[row * 256 + t];
    float m = blockSum256(x, red) * (1.f / 256.f);
    float d = x - m;
    float var = blockSum256(d * d, red) * (1.f / 256.f);
    out[row * 256 + t] = d * rsqrtf(var + 1e-5f) * g[t] + b[t];
}

// ================= tf32 tensor-core GEMM, cp.async double-buffered =================
// 128 threads = 4 warps (2x2), BM=64, BK=32, BN templated (32 or 64).
// Warp tile 32 x (BN/2).
// MODE 0: C = A@W + bias
// MODE 1: C = gelu(A@W + bias)
// MODE 2: QKV: cols [0,512)->W(ldw), [512,1536)->W2(ldw2); rotary on cols<1024
template<int MODE, int BN>
__global__ __launch_bounds__(128) void gemm_tc(
        const float* __restrict__ A, const float* __restrict__ W,
        const float* __restrict__ W2,
        const float* __restrict__ bias, const float* __restrict__ bias2,
        float* __restrict__ C, int N, int K, int ldw, int ldw2) {
    constexpr int BNPAD = BN + 8;
    constexpr int NT = BN / 16;           // n-tiles of 8 per warp
    __shared__ __align__(16) float As[2][64 * 36];
    __shared__ __align__(16) float Bs[2][32 * BNPAD];
    int tid = threadIdx.x;
    int lane = tid & 31, wid = tid >> 5;
    int wm = wid >> 1, wn = wid & 1;
    int g = lane >> 2, tig = lane & 3;
    int mo = blockIdx.y * 64, no = blockIdx.x * BN;

    const float* Wb = W;
    const float* bp = bias;
    int ld = ldw, noff = no;
    if (MODE == 2 && no >= 512) { Wb = W2; ld = ldw2; noff = no - 512; bp = bias2 - 512; }

    float acc[2][NT][4];
#pragma unroll
    for (int mt = 0; mt < 2; mt++)
#pragma unroll
        for (int nt = 0; nt < NT; nt++)
#pragma unroll
            for (int v = 0; v < 4; v++) acc[mt][nt][v] = 0.f;

    auto issue = [&](int kt, int st) {
        int k0 = kt * 32;
        // A tile 64x32 (raw fp32)
#pragma unroll
        for (int i = 0; i < 4; i++) {
            int q = tid + i * 128;
            int row = q >> 3, c = q & 7;
            cpasync16(&As[st][row * 36 + c * 4], &A[(mo + row) * K + k0 + c * 4]);
        }
        // B tile 32k x BN (row-major [k][n])
        if (BN == 64) {
#pragma unroll
            for (int i = 0; i < 4; i++) {
                int q = tid + i * 128;
                int k = q >> 4, c = q & 15;
                cpasync16(&Bs[st][k * BNPAD + c * 4], &Wb[(k0 + k) * ld + noff + c * 4]);
            }
        } else {
#pragma unroll
            for (int i = 0; i < 2; i++) {
                int q = tid + i * 128;
                int k = q >> 3, c = q & 7;
                cpasync16(&Bs[st][k * BNPAD + c * 4], &Wb[(k0 + k) * ld + noff + c * 4]);
            }
        }
    };

    int KT = K / 32;
    issue(0, 0);
    CP_COMMIT();
    for (int kt = 0; kt < KT; kt++) {
        int st = kt & 1;
        if (kt + 1 < KT) {
            issue(kt + 1, 1 - st);
            CP_COMMIT();
            CP_WAIT1();
        } else {
            CP_WAIT0();
        }
        __syncthreads();
#pragma unroll
        for (int ks = 0; ks < 4; ks++) {
            unsigned af[2][4];
#pragma unroll
            for (int mt = 0; mt < 2; mt++) {
                int rb = wm * 32 + mt * 16;
                af[mt][0] = f2tf(As[st][(rb + g) * 36 + ks * 8 + tig]);
                af[mt][1] = f2tf(As[st][(rb + g + 8) * 36 + ks * 8 + tig]);
                af[mt][2] = f2tf(As[st][(rb + g) * 36 + ks * 8 + tig + 4]);
                af[mt][3] = f2tf(As[st][(rb + g + 8) * 36 + ks * 8 + tig + 4]);
            }
            unsigned bf[NT][2];
#pragma unroll
            for (int nt = 0; nt < NT; nt++) {
                int cb2 = wn * (BN / 2) + nt * 8;
                bf[nt][0] = f2tf(Bs[st][(ks * 8 + tig) * BNPAD + cb2 + g]);
                bf[nt][1] = f2tf(Bs[st][(ks * 8 + tig + 4) * BNPAD + cb2 + g]);
            }
#pragma unroll
            for (int mt = 0; mt < 2; mt++)
#pragma unroll
                for (int nt = 0; nt < NT; nt++) {
                    asm volatile(
                        "mma.sync.aligned.m16n8k8.row.col.f32.tf32.tf32.f32 "
                        "{%0,%1,%2,%3}, {%4,%5,%6,%7}, {%8,%9}, {%0,%1,%2,%3};"
                        : "+f"(acc[mt][nt][0]), "+f"(acc[mt][nt][1]),
                          "+f"(acc[mt][nt][2]), "+f"(acc[mt][nt][3])
                        : "r"(af[mt][0]), "r"(af[mt][1]), "r"(af[mt][2]), "r"(af[mt][3]),
                          "r"(bf[nt][0]), "r"(bf[nt][1]));
                }
        }
        __syncthreads();
    }

    // epilogue
#pragma unroll
    for (int mt = 0; mt < 2; mt++) {
#pragma unroll
        for (int nt = 0; nt < NT; nt++) {
            int row0 = mo + wm * 32 + mt * 16 + g;
            int col0 = no + wn * (BN / 2) + nt * 8 + 2 * tig;
            float v0 = acc[mt][nt][0], v1 = acc[mt][nt][1];
            float v2 = acc[mt][nt][2], v3 = acc[mt][nt][3];
            v0 += bp[col0]; v1 += bp[col0 + 1];
            v2 += bp[col0]; v3 += bp[col0 + 1];
            if (MODE == 1) {
                v0 = 0.5f * v0 * (1.f + erff(v0 * 0.70710678118654752f));
                v1 = 0.5f * v1 * (1.f + erff(v1 * 0.70710678118654752f));
                v2 = 0.5f * v2 * (1.f + erff(v2 * 0.70710678118654752f));
                v3 = 0.5f * v3 * (1.f + erff(v3 * 0.70710678118654752f));
            }
            if (MODE == 2 && no < 1024) {
                int d0 = col0 & 63;
                float inv = expf(-((float)d0 / 64.f) * LN10000);
                float s0, c0, s1, c1;
                sincosf((float)(row0 & 127) * inv, &s0, &c0);
                sincosf((float)((row0 + 8) & 127) * inv, &s1, &c1);
                float x1 = v0, x2 = v1;
                v0 = x1 * c0 - x2 * s0;
                v1 = x2 * c0 + x1 * s0;
                x1 = v2; x2 = v3;
                v2 = x1 * c1 - x2 * s1;
                v3 = x2 * c1 + x1 * s1;
            }
            float2 p0; p0.x = v0; p0.y = v1;
            float2 p1; p1.x = v2; p1.y = v3;
            *(float2*)&C[row0 * N + col0] = p0;
            *(float2*)&C[(row0 + 8) * N + col0] = p1;
        }
    }
}

// ---------------- fp32 SIMT GEMM (kept for VQ scores: C = A @ W^T) ----------------
__global__ __launch_bounds__(64) void gemm_vq_kernel(
        const float* __restrict__ A, const float* __restrict__ W,
        float* __restrict__ C, int N, int K) {
    constexpr int BM = 64;
    constexpr int APAD = BM + 4;
    __shared__ __align__(16) float As[16 * APAD];
    __shared__ __align__(16) float Bs[16 * 36];
    int tid = threadIdx.x;
    int tx = tid & 7, ty = tid >> 3;
    int mo = blockIdx.y * BM, no = blockIdx.x * 32;
    float acc[8][4] = {};
    for (int k0 = 0; k0 < K; k0 += 16) {
#pragma unroll
        for (int l = 0; l < 4; l++) {
            int q = tid + l * 64;
            int row = q >> 2, c4 = q & 3;
            float4 f = *(const float4*)&A[(mo + row) * K + k0 + c4 * 4];
            As[(c4 * 4 + 0) * APAD + row] = f.x;
            As[(c4 * 4 + 1) * APAD + row] = f.y;
            As[(c4 * 4 + 2) * APAD + row] = f.z;
            As[(c4 * 4 + 3) * APAD + row] = f.w;
        }
#pragma unroll
        for (int l = 0; l < 2; l++) {
            int q = tid + l * 64;
            int c = q >> 2, r4 = q & 3;
            float4 f = *(const float4*)&W[(no + c) * K + k0 + r4 * 4];
            Bs[(r4 * 4 + 0) * 36 + c] = f.x;
            Bs[(r4 * 4 + 1) * 36 + c] = f.y;
            Bs[(r4 * 4 + 2) * 36 + c] = f.z;
            Bs[(r4 * 4 + 3) * 36 + c] = f.w;
        }
        __syncthreads();
#pragma unroll
        for (int kk = 0; kk < 16; kk++) {
            float a[8];
            float4 a0 = *(const float4*)&As[kk * APAD + ty * 8];
            float4 a1 = *(const float4*)&As[kk * APAD + ty * 8 + 4];
            a[0] = a0.x; a[1] = a0.y; a[2] = a0.z; a[3] = a0.w;
            a[4] = a1.x; a[5] = a1.y; a[6] = a1.z; a[7] = a1.w;
            float4 b4 = *(const float4*)&Bs[kk * 36 + tx * 4];
            float b[4] = {b4.x, b4.y, b4.z, b4.w};
#pragma unroll
            for (int u = 0; u < 8; u++)
#pragma unroll
                for (int v = 0; v < 4; v++) acc[u][v] += a[u] * b[v];
        }
        __syncthreads();
    }
#pragma unroll
    for (int u = 0; u < 8; u++) {
        int row = mo + ty * 8 + u;
        float4 r;
        r.x = acc[u][0]; r.y = acc[u][1]; r.z = acc[u][2]; r.w = acc[u][3];
        *(float4*)&C[row * N + no + tx * 4] = r;
    }
}

// ---- fused qw + sim_e: qw[h,c] = sum_d q[h*64+d]*wekv[c,h*64+d];
//      sime[b,i,j,h] = sum_c qw[h,c]*e[b,i,j,c] ----
__global__ void sime_kernel(const float* __restrict__ e, const float* __restrict__ qkv,
                            const float* __restrict__ wekv, float* __restrict__ sime) {
    __shared__ float esm[128 * 65];
    __shared__ float qs[512];
    __shared__ float qwsm[8 * 66];
    int bi = blockIdx.x, tid = threadIdx.x;
    qs[tid] = qkv[bi * 1536 + tid];
    qs[tid + 256] = qkv[bi * 1536 + 256 + tid];
    const float* ep = e + (size_t)bi * 8192;
    for (int idx = tid; idx < 8192; idx += 256) {
        int j = idx >> 6, c = idx & 63;
        esm[j * 65 + c] = ep[idx];
    }
    __syncthreads();
    for (int idx = tid; idx < 512; idx += 256) {
        int h = idx >> 6, c = idx & 63;
        const float* wr = wekv + c * 512 + h * 64;
        const float* qh = qs + h * 64;
        float s = 0.f;
#pragma unroll 16
        for (int d = 0; d < 64; d++) s += qh[d] * wr[d];
        qwsm[h * 66 + c] = s;
    }
    __syncthreads();
    for (int idx = tid; idx < 1024; idx += 256) {
        int h = idx & 7, j = idx >> 3;
        float s = 0.f;
#pragma unroll 16
        for (int c = 0; c < 64; c++) s += qwsm[h * 66 + c] * esm[j * 65 + c];
        sime[bi * 1024 + idx] = s;
    }
}

// ---------------- attention core: per (b,h), chunk of 16 i ----------------
#define ATTN_SMEM ((128*65 + 128*64) * 4)
__global__ void attn_kernel(const float* __restrict__ qkv,
                            const float* __restrict__ sime,
                            float* __restrict__ att, float* __restrict__ aout) {
    extern __shared__ float dyn[];
    float* ksm = dyn;                 // 128*65
    float* vsm = dyn + 128 * 65;      // 128*64
    __shared__ float qs[64], attsm[128], psm[128], redm[4], reds[4];
    int bh = blockIdx.x;
    int b = bh >> 3, h = bh & 7;
    int i0 = blockIdx.y * 16;
    int tid = threadIdx.x, lane = tid & 31, w = tid >> 5;
    for (int idx = tid; idx < 8192; idx += 128) {
        int j = idx >> 6, d = idx & 63;
        ksm[j * 65 + d] = qkv[(b * 128 + j) * 1536 + 512 + h * 64 + d];
        vsm[j * 64 + d] = qkv[(b * 128 + j) * 1536 + 1024 + h * 64 + d];
    }
    __syncthreads();
    for (int ii = 0; ii < 16; ii++) {
        int i = i0 + ii;
        int bi = b * 128 + i;
        if (tid < 64) qs[tid] = qkv[bi * 1536 + h * 64 + tid];
        __syncthreads();
        int j = tid;
        float sim = sime[(bi * 128 + j) * 8 + h];
#pragma unroll 16
        for (int d = 0; d < 64; d++) sim += qs[d] * ksm[j * 65 + d];
        sim *= 0.125f;
        float m = sim;
#pragma unroll
        for (int o = 16; o; o >>= 1) m = fmaxf(m, __shfl_xor_sync(0xffffffffu, m, o));
        if (!lane) redm[w] = m;
        __syncthreads();
        m = fmaxf(fmaxf(redm[0], redm[1]), fmaxf(redm[2], redm[3]));
        float ex = expf(sim - m);
        float s = ex;
#pragma unroll
        for (int o = 16; o; o >>= 1) s += __shfl_xor_sync(0xffffffffu, s, o);
        if (!lane) reds[w] = s;
        __syncthreads();
        s = reds[0] + reds[1] + reds[2] + reds[3];
        float a = ex / s;
        attsm[tid] = a;
        att[(bi * 8 + h) * 128 + tid] = a;
        __syncthreads();
        int gg = tid >> 6, d = tid & 63;
        float acc = 0.f;
#pragma unroll 16
        for (int jj = 0; jj < 64; jj++) acc += attsm[gg * 64 + jj] * vsm[(gg * 64 + jj) * 64 + d];
        psm[tid] = acc;
        __syncthreads();
        if (tid < 64) aout[bi * 512 + h * 64 + tid] = psm[tid] + psm[64 + tid];
        __syncthreads();
    }
}

// ---------------- edge output: ae = att @ e ; aout += ae @ w_ekv + b_ekv ----------------
__global__ void edgeout_kernel(const float* __restrict__ e, const float* __restrict__ att,
                               const float* __restrict__ wekv, const float* __restrict__ bekv,
                               float* __restrict__ aout) {
    __shared__ float esm[128 * 65];
    __shared__ float asmem[8 * 128];
    __shared__ float aesm[8 * 66];
    int bi = blockIdx.x, tid = threadIdx.x;
    const float* ep = e + (size_t)bi * 8192;
    for (int idx = tid; idx < 8192; idx += 256) {
        int j = idx >> 6, c = idx & 63;
        esm[j * 65 + c] = ep[idx];
    }
    for (int idx = tid; idx < 1024; idx += 256) asmem[idx] = att[bi * 1024 + idx];
    __syncthreads();
    for (int idx = tid; idx < 512; idx += 256) {
        int h = idx >> 6, c = idx & 63;
        float s = 0.f;
#pragma unroll 16
        for (int j = 0; j < 128; j++) s += asmem[h * 128 + j] * esm[j * 65 + c];
        aesm[h * 66 + c] = s;
    }
    __syncthreads();
    for (int idx = tid; idx < 512; idx += 256) {
        int h = idx >> 6, d = idx & 63;
        float s = bekv[idx];
#pragma unroll 16
        for (int c = 0; c < 64; c++) s += aesm[h * 66 + c] * wekv[c * 512 + h * 64 + d];
        aout[bi * 512 + idx] += s;
    }
}

// ---------------- gated residual (in-place) + optional fused LayerNorm ----------------
__global__ void gate_ln_kernel(const float* __restrict__ x, float* __restrict__ nodes,
                               const float* __restrict__ gw,
                               const float* __restrict__ lng, const float* __restrict__ lnb,
                               float* __restrict__ lnout) {
    __shared__ float red[8];
    int row = blockIdx.x, t = threadIdx.x;
    float xv = x[row * 256 + t];
    float rv = nodes[row * 256 + t];
    float contrib = xv * gw[t] + rv * gw[256 + t] + (xv - rv) * gw[512 + t];
    float s = blockSum256(contrib, red);
    float gate = 1.f / (1.f + expf(-s));
    float nn = xv * gate + rv * (1.f - gate);
    nodes[row * 256 + t] = nn;
    if (lng) {
        float m = blockSum256(nn, red) * (1.f / 256.f);
        float d = nn - m;
        float var = blockSum256(d * d, red) * (1.f / 256.f);
        lnout[row * 256 + t] = d * rsqrtf(var + 1e-5f) * lng[t] + lnb[t];
    }
}

// ---------------- codebook squared norms ----------------
__global__ void cnorm_kernel(const float* __restrict__ cb, float* __restrict__ cn) {
    __shared__ float red[8];
    int k = blockIdx.x, t = threadIdx.x;
    float v = cb[k * 256 + t];
    float s = blockSum256(v * v, red);
    if (!t) cn[k] = s;
}

// ---------------- argmin + gather ----------------
__global__ void vq_kernel(const float* __restrict__ S, const float* __restrict__ cn,
                          const float* __restrict__ cb, const float* __restrict__ z,
                          float* __restrict__ out) {
    __shared__ float bv[256];
    __shared__ int bix[256];
    int r = blockIdx.x, t = threadIdx.x;
    float best = 1e30f; int bidx = 0;
    for (int k = t; k < 512; k += 256) {
        float v = cn[k] - 2.f * S[r * 512 + k];
        if (v < best) { best = v; bidx = k; }
    }
    bv[t] = best; bix[t] = bidx;
    __syncthreads();
    for (int s = 128; s; s >>= 1) {
        if (t < s) {
            float v2 = bv[t + s]; int i2 = bix[t + s];
            if (v2 < bv[t] || (v2 == bv[t] && i2 < bix[t])) { bv[t] = v2; bix[t] = i2; }
        }
        __syncthreads();
    }
    int k = bix[0];
    float zz = z[r * 256 + t];
    out[r * 256 + t] = zz + (cb[k * 256 + t] - zz);
}

// ---------------- host launch ----------------
extern "C" void kernel_launch(void* const* d_in, const int* in_sizes, int n_in,
                              void* d_out, int out_size) {
    const float* in_nodes = (const float*)d_in[0];
    const float* edges   = (const float*)d_in[1];
    const float* eg      = (const float*)d_in[2];
    const float* ebias   = (const float*)d_in[3];
    const float* ln1g    = (const float*)d_in[4];
    const float* ln1b    = (const float*)d_in[5];
    const float* wexp    = (const float*)d_in[6];
    const float* bexp    = (const float*)d_in[7];
    const float* wq      = (const float*)d_in[8];
    const float* bq      = (const float*)d_in[9];
    const float* wkv     = (const float*)d_in[10];
    const float* bkv     = (const float*)d_in[11];
    const float* wekv    = (const float*)d_in[12];
    const float* bekv    = (const float*)d_in[13];
    const float* wout    = (const float*)d_in[14];
    const float* bout    = (const float*)d_in[15];
    const float* g1      = (const float*)d_in[16];
    const float* ln2g    = (const float*)d_in[17];
    const float* ln2b    = (const float*)d_in[18];
    const float* wff1    = (const float*)d_in[19];
    const float* bff1    = (const float*)d_in[20];
    const float* wff2    = (const float*)d_in[21];
    const float* bff2    = (const float*)d_in[22];
    const float* g2      = (const float*)d_in[23];
    const float* cb      = (const float*)d_in[24];
    float* out = (float*)d_out;

    float* S;
    cudaGetSymbolAddress((void**)&S, g_scratch);
    float* E     = S + E_OFF;
    float* NODES = S + NODES_OFF;
    float* XN    = S + XN_OFF;
    float* XE    = S + XE_OFF;
    float* QKV   = S + QKV_OFF;
    float* SIME  = S + SIME_OFF;
    float* ATT   = S + ATT_OFF;
    float* AOUT  = S + AOUT_OFF;
    float* OUT2  = S + OUT2_OFF;
    float* H1    = S + H1_OFF;
    float* H2    = S + H2_OFF;
    float* CN    = S + CN_OFF;

    cudaFuncSetAttribute(attn_kernel, cudaFuncAttributeMaxDynamicSharedMemorySize, ATTN_SMEM);

    cudaMemcpyAsync(NODES, in_nodes, (size_t)ROWS * 256 * sizeof(float),
                    cudaMemcpyDeviceToDevice);

    edge_ln_kernel<<<512, 256>>>(edges, eg, ebias, E);
    ln_rows_kernel<<<512, 256>>>(NODES, ln1g, ln1b, XN);

    for (int l = 0; l < 2; l++) {
        // XE = XN @ wexp + bexp          (512x512, K=256)
        gemm_tc<0, 32><<<dim3(16, 8), 128>>>(XN, wexp + l * 131072, nullptr,
                                             bexp + l * 512, nullptr, XE, 512, 256, 512, 0);
        // QKV = XE @ [wq | wkv] + bias, rotary on Q,K   (512x1536, K=512)
        gemm_tc<2, 64><<<dim3(24, 8), 128>>>(XE, wq + l * 262144, wkv + l * 524288,
                                             bq + l * 512, bkv + l * 1024, QKV,
                                             1536, 512, 512, 1024);
        sime_kernel<<<512, 256>>>(E, QKV, wekv + l * 32768, SIME);
        attn_kernel<<<dim3(32, 8), 128, ATTN_SMEM>>>(QKV, SIME, ATT, AOUT);
        edgeout_kernel<<<512, 256>>>(E, ATT, wekv + l * 32768, bekv + l * 512, AOUT);
        // OUT2 = AOUT @ wout + bout      (512x256, K=512)
        gemm_tc<0, 32><<<dim3(8, 8), 128>>>(AOUT, wout + l * 131072, nullptr,
                                            bout + l * 256, nullptr, OUT2, 256, 512, 256, 0);
        gate_ln_kernel<<<512, 256>>>(OUT2, NODES, g1 + l * 768,
                                     ln2g + l * 256, ln2b + l * 256, XN);
        // H1 = gelu(XN @ wff1 + bff1)    (512x1024, K=256)
        gemm_tc<1, 64><<<dim3(16, 8), 128>>>(XN, wff1 + l * 262144, nullptr,
                                             bff1 + l * 1024, nullptr, H1, 1024, 256, 1024, 0);
        // H2 = H1 @ wff2 + bff2          (512x256, K=1024)
        gemm_tc<0, 32><<<dim3(8, 8), 128>>>(H1, wff2 + l * 262144, nullptr,
                                            bff2 + l * 256, nullptr, H2, 256, 1024, 256, 0);
        if (l == 0) {
            gate_ln_kernel<<<512, 256>>>(H2, NODES, g2 + l * 768,
                                         ln1g + 256, ln1b + 256, XN);
        } else {
            gate_ln_kernel<<<512, 256>>>(H2, NODES, g2 + l * 768,
                                         nullptr, nullptr, nullptr);
        }
    }

    cnorm_kernel<<<512, 256>>>(cb, CN);
    // VQ scores: S = NODES @ cb^T (fp32 SIMT — argmin precision)  (512x512, K=256)
    gemm_vq_kernel<<<dim3(16, 8), 64>>>(NODES, cb, XE, 512, 256);
    vq_kernel<<<512, 256>>>(XE, CN, cb, NODES, out);
}

// round 12
// speedup vs baseline: 1.4471x; 1.0651x over previous
#include <cuda_runtime.h>
#include <cuda_bf16.h>
#include <math.h>

// Problem constants
#define BB   4
#define NN   128
#define DIM  256
#define HH   8
#define DHH  64
#define EE   64
#define INNER 512
#define ROWS 512          // B*N
#define LN10000 9.210340371976184f

// ---------------- scratch (one big static device buffer) ----------------
#define E_OFF     0            // 4*128*128*64 = 4194304  (edge LN result, (b,i,j,c))
#define NODES_OFF 4194304      // 131072
#define XN_OFF    4325376      // 131072
#define XE_OFF    4456448      // 262144 (also VQ scores 512x512)
#define QKV_OFF   4718592      // 512*1536 = 786432  [Q | K | V] rotated
#define SIME_OFF  5767168      // 524288  (b,i,j,h)
#define ATT_OFF   6291456      // 524288  (b,i,h,j)
#define AOUT_OFF  6815744      // 262144
#define OUT2_OFF  7077888      // 131072
#define H1_OFF    7208960      // 524288
#define H2_OFF    7733248      // 131072
#define CN_OFF    7864320      // 512
#define SCRATCH_FLOATS 7864832

__device__ float g_scratch[SCRATCH_FLOATS];

// ---------------- reductions ----------------
__device__ __forceinline__ float blockSum256(float v, float* red8) {
    int lane = threadIdx.x & 31, w = threadIdx.x >> 5;
#pragma unroll
    for (int o = 16; o; o >>= 1) v += __shfl_xor_sync(0xffffffffu, v, o);
    if (!lane) red8[w] = v;
    __syncthreads();
    float t = (threadIdx.x < 8) ? red8[threadIdx.x] : 0.f;
    if (w == 0) {
#pragma unroll
        for (int o = 4; o; o >>= 1) t += __shfl_xor_sync(0xffffffffu, t, o);
        if (!lane) red8[0] = t;
    }
    __syncthreads();
    v = red8[0];
    __syncthreads();
    return v;
}

__device__ __forceinline__ unsigned f2tf(float x) {
    unsigned r;
    asm("cvt.rna.tf32.f32 %0, %1;" : "=r"(r) : "f"(x));
    return r;
}

__device__ __forceinline__ void cpasync16(void* smem_dst, const void* gsrc) {
    unsigned s = (unsigned)__cvta_generic_to_shared(smem_dst);
    asm volatile("cp.async.cg.shared.global [%0], [%1], 16;\n" :: "r"(s), "l"(gsrc));
}
#define CP_COMMIT() asm volatile("cp.async.commit_group;\n" ::: "memory")
#define CP_WAIT1()  asm volatile("cp.async.wait_group 1;\n" ::: "memory")
#define CP_WAIT0()  asm volatile("cp.async.wait_group 0;\n" ::: "memory")

// ---------------- edge LayerNorm: edges (B,E,N,N) -> e (B,N,N,E) ----------------
__global__ void edge_ln_kernel(const float* __restrict__ edges,
                               const float* __restrict__ g, const float* __restrict__ b,
                               float* __restrict__ e) {
    __shared__ float s[64 * 129];
    __shared__ float mn[128], rs[128];
    int bi = blockIdx.x;              // b*128 + i
    int bidx = bi >> 7, i = bi & 127;
    int tid = threadIdx.x;
    for (int idx = tid; idx < 8192; idx += 256) {
        int c = idx >> 7, j = idx & 127;
        s[c * 129 + j] = edges[((bidx * 64 + c) * 128 + i) * 128 + j];
    }
    __syncthreads();
    if (tid < 128) {
        int j = tid;
        float sum = 0.f;
#pragma unroll 16
        for (int c = 0; c < 64; c++) sum += s[c * 129 + j];
        float m = sum * (1.f / 64.f);
        float var = 0.f;
#pragma unroll 16
        for (int c = 0; c < 64; c++) { float d = s[c * 129 + j] - m; var += d * d; }
        var *= (1.f / 64.f);
        mn[j] = m;
        rs[j] = rsqrtf(var + 1e-5f);
    }
    __syncthreads();
    float* ep = e + (size_t)bi * 8192;
    for (int idx = tid; idx < 8192; idx += 256) {
        int j = idx >> 6, c = idx & 63;
        ep[idx] = (s[c * 129 + j] - mn[j]) * rs[j] * g[c] + b[c];
    }
}

// ---------------- row LayerNorm over 256 ----------------
__global__ void ln_rows_kernel(const float* __restrict__ in,
                               const float* __restrict__ g, const float* __restrict__ b,
                               float* __restrict__ out) {
    __shared__ float red[8];
    int row = blockIdx.x, t = threadIdx.x;
    float x = in[row * 256 + t];
    float m = blockSum256(x, red) * (1.f / 256.f);
    float d = x - m;
    float var = blockSum256(d * d, red) * (1.f / 256.f);
    out[row * 256 + t] = d * rsqrtf(var + 1e-5f) * g[t] + b[t];
}

// ================= tf32 tensor-core GEMM, cp.async double-buffered =================
// 128 threads = 4 warps. BM in {32,64}, BN in {32,64}.
// BM=64: warps 2x2 (warp tile 32 x BN/2). BM=32: warps 1x4 (warp tile 32 x BN/4).
// MODE 0: C = A@W + bias
// MODE 1: C = gelu(A@W + bias)
// MODE 2: QKV: cols [0,512)->W(ldw), [512,1536)->W2(ldw2); rotary on cols<1024
template<int MODE, int BM, int BN>
__global__ __launch_bounds__(128) void gemm_tc(
        const float* __restrict__ A, const float* __restrict__ W,
        const float* __restrict__ W2,
        const float* __restrict__ bias, const float* __restrict__ bias2,
        float* __restrict__ C, int N, int K, int ldw, int ldw2) {
    constexpr int BNPAD = BN + 8;
    constexpr int WM = (BM == 64) ? 2 : 1;
    constexpr int WN = 4 / WM;
    constexpr int WTN = BN / WN;          // cols per warp
    constexpr int NT = WTN / 8;           // n-tiles of 8 per warp
    __shared__ __align__(16) float As[2][BM * 36];
    __shared__ __align__(16) float Bs[2][32 * BNPAD];
    int tid = threadIdx.x;
    int lane = tid & 31, wid = tid >> 5;
    int wm = wid / WN, wn = wid % WN;
    int g = lane >> 2, tig = lane & 3;
    int mo = blockIdx.y * BM, no = blockIdx.x * BN;

    const float* Wb = W;
    const float* bp = bias;
    int ld = ldw, noff = no;
    if (MODE == 2 && no >= 512) { Wb = W2; ld = ldw2; noff = no - 512; bp = bias2 - 512; }

    float acc[2][NT][4];
#pragma unroll
    for (int mt = 0; mt < 2; mt++)
#pragma unroll
        for (int nt = 0; nt < NT; nt++)
#pragma unroll
            for (int v = 0; v < 4; v++) acc[mt][nt][v] = 0.f;

    auto issue = [&](int kt, int st) {
        int k0 = kt * 32;
        // A tile BMx32 (raw fp32)
#pragma unroll
        for (int i = 0; i < BM / 16; i++) {
            int q = tid + i * 128;
            int row = q >> 3, c = q & 7;
            cpasync16(&As[st][row * 36 + c * 4], &A[(mo + row) * K + k0 + c * 4]);
        }
        // B tile 32k x BN (row-major [k][n])
        if (BN == 64) {
#pragma unroll
            for (int i = 0; i < 4; i++) {
                int q = tid + i * 128;
                int k = q >> 4, c = q & 15;
                cpasync16(&Bs[st][k * BNPAD + c * 4], &Wb[(k0 + k) * ld + noff + c * 4]);
            }
        } else {
#pragma unroll
            for (int i = 0; i < 2; i++) {
                int q = tid + i * 128;
                int k = q >> 3, c = q & 7;
                cpasync16(&Bs[st][k * BNPAD + c * 4], &Wb[(k0 + k) * ld + noff + c * 4]);
            }
        }
    };

    int KT = K / 32;
    issue(0, 0);
    CP_COMMIT();
    for (int kt = 0; kt < KT; kt++) {
        int st = kt & 1;
        if (kt + 1 < KT) {
            issue(kt + 1, 1 - st);
            CP_COMMIT();
            CP_WAIT1();
        } else {
            CP_WAIT0();
        }
        __syncthreads();
#pragma unroll
        for (int ks = 0; ks < 4; ks++) {
            unsigned af[2][4];
#pragma unroll
            for (int mt = 0; mt < 2; mt++) {
                int rb = wm * 32 + mt * 16;
                af[mt][0] = f2tf(As[st][(rb + g) * 36 + ks * 8 + tig]);
                af[mt][1] = f2tf(As[st][(rb + g + 8) * 36 + ks * 8 + tig]);
                af[mt][2] = f2tf(As[st][(rb + g) * 36 + ks * 8 + tig + 4]);
                af[mt][3] = f2tf(As[st][(rb + g + 8) * 36 + ks * 8 + tig + 4]);
            }
            unsigned bf[NT][2];
#pragma unroll
            for (int nt = 0; nt < NT; nt++) {
                int cb2 = wn * WTN + nt * 8;
                bf[nt][0] = f2tf(Bs[st][(ks * 8 + tig) * BNPAD + cb2 + g]);
                bf[nt][1] = f2tf(Bs[st][(ks * 8 + tig + 4) * BNPAD + cb2 + g]);
            }
#pragma unroll
            for (int mt = 0; mt < 2; mt++)
#pragma unroll
                for (int nt = 0; nt < NT; nt++) {
                    asm volatile(
                        "mma.sync.aligned.m16n8k8.row.col.f32.tf32.tf32.f32 "
                        "{%0,%1,%2,%3}, {%4,%5,%6,%7}, {%8,%9}, {%0,%1,%2,%3};"
                        : "+f"(acc[mt][nt][0]), "+f"(acc[mt][nt][1]),
                          "+f"(acc[mt][nt][2]), "+f"(acc[mt][nt][3])
                        : "r"(af[mt][0]), "r"(af[mt][1]), "r"(af[mt][2]), "r"(af[mt][3]),
                          "r"(bf[nt][0]), "r"(bf[nt][1]));
                }
        }
        __syncthreads();
    }

    // epilogue
#pragma unroll
    for (int mt = 0; mt < 2; mt++) {
#pragma unroll
        for (int nt = 0; nt < NT; nt++) {
            int row0 = mo + wm * 32 + mt * 16 + g;
            int col0 = no + wn * WTN + nt * 8 + 2 * tig;
            float v0 = acc[mt][nt][0], v1 = acc[mt][nt][1];
            float v2 = acc[mt][nt][2], v3 = acc[mt][nt][3];
            v0 += bp[col0]; v1 += bp[col0 + 1];
            v2 += bp[col0]; v3 += bp[col0 + 1];
            if (MODE == 1) {
                v0 = 0.5f * v0 * (1.f + erff(v0 * 0.70710678118654752f));
                v1 = 0.5f * v1 * (1.f + erff(v1 * 0.70710678118654752f));
                v2 = 0.5f * v2 * (1.f + erff(v2 * 0.70710678118654752f));
                v3 = 0.5f * v3 * (1.f + erff(v3 * 0.70710678118654752f));
            }
            if (MODE == 2 && no < 1024) {
                int d0 = col0 & 63;
                float inv = expf(-((float)d0 / 64.f) * LN10000);
                float s0, c0, s1, c1;
                sincosf((float)(row0 & 127) * inv, &s0, &c0);
                sincosf((float)((row0 + 8) & 127) * inv, &s1, &c1);
                float x1 = v0, x2 = v1;
                v0 = x1 * c0 - x2 * s0;
                v1 = x2 * c0 + x1 * s0;
                x1 = v2; x2 = v3;
                v2 = x1 * c1 - x2 * s1;
                v3 = x2 * c1 + x1 * s1;
            }
            float2 p0; p0.x = v0; p0.y = v1;
            float2 p1; p1.x = v2; p1.y = v3;
            *(float2*)&C[row0 * N + col0] = p0;
            *(float2*)&C[(row0 + 8) * N + col0] = p1;
        }
    }
}

// ---------------- VQ scores via 3xTF32 (fp32-accurate): C = A @ W^T ----------------
// M=512, N=512, K=256. BM=64, BN=64, 128 threads (2x2 warps, warp tile 32x32).
__global__ __launch_bounds__(128) void gemm_vq_tc(
        const float* __restrict__ A, const float* __restrict__ W,
        float* __restrict__ C) {
    constexpr int K = 256, N = 512;
    __shared__ __align__(16) float As[2][64 * 36];
    __shared__ __align__(16) float Bs[2][64 * 36];   // Bs[n][k]
    int tid = threadIdx.x;
    int lane = tid & 31, wid = tid >> 5;
    int wm = wid >> 1, wn = wid & 1;
    int g = lane >> 2, tig = lane & 3;
    int mo = blockIdx.y * 64, no = blockIdx.x * 64;

    float acc[2][4][4];
#pragma unroll
    for (int mt = 0; mt < 2; mt++)
#pragma unroll
        for (int nt = 0; nt < 4; nt++)
#pragma unroll
            for (int v = 0; v < 4; v++) acc[mt][nt][v] = 0.f;

    auto issue = [&](int kt, int st) {
        int k0 = kt * 32;
#pragma unroll
        for (int i = 0; i < 4; i++) {
            int q = tid + i * 128;
            int row = q >> 3, c = q & 7;
            cpasync16(&As[st][row * 36 + c * 4], &A[(mo + row) * K + k0 + c * 4]);
            cpasync16(&Bs[st][row * 36 + c * 4], &W[(no + row) * K + k0 + c * 4]);
        }
    };

    issue(0, 0);
    CP_COMMIT();
    for (int kt = 0; kt < 8; kt++) {
        int st = kt & 1;
        if (kt + 1 < 8) {
            issue(kt + 1, 1 - st);
            CP_COMMIT();
            CP_WAIT1();
        } else {
            CP_WAIT0();
        }
        __syncthreads();
#pragma unroll
        for (int ks = 0; ks < 4; ks++) {
            unsigned ah[2][4], al[2][4];
#pragma unroll
            for (int mt = 0; mt < 2; mt++) {
                int rb = wm * 32 + mt * 16;
                float x0 = As[st][(rb + g) * 36 + ks * 8 + tig];
                float x1 = As[st][(rb + g + 8) * 36 + ks * 8 + tig];
                float x2 = As[st][(rb + g) * 36 + ks * 8 + tig + 4];
                float x3 = As[st][(rb + g + 8) * 36 + ks * 8 + tig + 4];
                ah[mt][0] = f2tf(x0); al[mt][0] = f2tf(x0 - __uint_as_float(ah[mt][0]));
                ah[mt][1] = f2tf(x1); al[mt][1] = f2tf(x1 - __uint_as_float(ah[mt][1]));
                ah[mt][2] = f2tf(x2); al[mt][2] = f2tf(x2 - __uint_as_float(ah[mt][2]));
                ah[mt][3] = f2tf(x3); al[mt][3] = f2tf(x3 - __uint_as_float(ah[mt][3]));
            }
            unsigned bh_[4][2], bl_[4][2];
#pragma unroll
            for (int nt = 0; nt < 4; nt++) {
                int cb2 = wn * 32 + nt * 8;
                float y0 = Bs[st][(cb2 + g) * 36 + ks * 8 + tig];
                float y1 = Bs[st][(cb2 + g) * 36 + ks * 8 + tig + 4];
                bh_[nt][0] = f2tf(y0); bl_[nt][0] = f2tf(y0 - __uint_as_float(bh_[nt][0]));
                bh_[nt][1] = f2tf(y1); bl_[nt][1] = f2tf(y1 - __uint_as_float(bh_[nt][1]));
            }
#pragma unroll
            for (int mt = 0; mt < 2; mt++)
#pragma unroll
                for (int nt = 0; nt < 4; nt++) {
#define VQMMA(AA, BB0, BB1)                                                        \
                    asm volatile(                                                  \
                        "mma.sync.aligned.m16n8k8.row.col.f32.tf32.tf32.f32 "     \
                        "{%0,%1,%2,%3}, {%4,%5,%6,%7}, {%8,%9}, {%0,%1,%2,%3};"   \
                        : "+f"(acc[mt][nt][0]), "+f"(acc[mt][nt][1]),              \
                          "+f"(acc[mt][nt][2]), "+f"(acc[mt][nt][3])               \
                        : "r"(AA[mt][0]), "r"(AA[mt][1]), "r"(AA[mt][2]),          \
                          "r"(AA[mt][3]), "r"(BB0), "r"(BB1))
                    VQMMA(al, bh_[nt][0], bh_[nt][1]);
                    VQMMA(ah, bl_[nt][0], bl_[nt][1]);
                    VQMMA(ah, bh_[nt][0], bh_[nt][1]);
#undef VQMMA
                }
        }
        __syncthreads();
    }
#pragma unroll
    for (int mt = 0; mt < 2; mt++)
#pragma unroll
        for (int nt = 0; nt < 4; nt++) {
            int row0 = mo + wm * 32 + mt * 16 + g;
            int col0 = no + wn * 32 + nt * 8 + 2 * tig;
            float2 p0; p0.x = acc[mt][nt][0]; p0.y = acc[mt][nt][1];
            float2 p1; p1.x = acc[mt][nt][2]; p1.y = acc[mt][nt][3];
            *(float2*)&C[row0 * N + col0] = p0;
            *(float2*)&C[(row0 + 8) * N + col0] = p1;
        }
}

// ---- fused qw + sim_e: qw[h,c] = sum_d q[h*64+d]*wekv[c,h*64+d];
//      sime[b,i,j,h] = sum_c qw[h,c]*e[b,i,j,c] ----
__global__ void sime_kernel(const float* __restrict__ e, const float* __restrict__ qkv,
                            const float* __restrict__ wekv, float* __restrict__ sime) {
    __shared__ float esm[128 * 65];
    __shared__ float qs[512];
    __shared__ float qwsm[8 * 66];
    int bi = blockIdx.x, tid = threadIdx.x;
    qs[tid] = qkv[bi * 1536 + tid];
    qs[tid + 256] = qkv[bi * 1536 + 256 + tid];
    const float* ep = e + (size_t)bi * 8192;
    for (int idx = tid; idx < 8192; idx += 256) {
        int j = idx >> 6, c = idx & 63;
        esm[j * 65 + c] = ep[idx];
    }
    __syncthreads();
    for (int idx = tid; idx < 512; idx += 256) {
        int h = idx >> 6, c = idx & 63;
        const float* wr = wekv + c * 512 + h * 64;
        const float* qh = qs + h * 64;
        float s = 0.f;
#pragma unroll 16
        for (int d = 0; d < 64; d++) s += qh[d] * wr[d];
        qwsm[h * 66 + c] = s;
    }
    __syncthreads();
    for (int idx = tid; idx < 1024; idx += 256) {
        int h = idx & 7, j = idx >> 3;
        float s = 0.f;
#pragma unroll 16
        for (int c = 0; c < 64; c++) s += qwsm[h * 66 + c] * esm[j * 65 + c];
        sime[bi * 1024 + idx] = s;
    }
}

// ---------------- attention core: per (b,h), 256 threads = 2 i-groups ----------------
#define ATTN_SMEM ((128*65 + 128*64) * 4)
__global__ void attn_kernel(const float* __restrict__ qkv,
                            const float* __restrict__ sime,
                            float* __restrict__ att, float* __restrict__ aout) {
    extern __shared__ float dyn[];
    float* ksm = dyn;                 // 128*65
    float* vsm = dyn + 128 * 65;      // 128*64
    __shared__ float qs[2][64], attsm[2][128], psm[2][128], redm[2][4], reds[2][4];
    int bh = blockIdx.x;
    int b = bh >> 3, h = bh & 7;
    int i0 = blockIdx.y * 16;
    int tid = threadIdx.x;
    int grp = tid >> 7, t = tid & 127;
    int lane = t & 31, w = t >> 5;
    for (int idx = tid; idx < 8192; idx += 256) {
        int j = idx >> 6, d = idx & 63;
        ksm[j * 65 + d] = qkv[(b * 128 + j) * 1536 + 512 + h * 64 + d];
        vsm[j * 64 + d] = qkv[(b * 128 + j) * 1536 + 1024 + h * 64 + d];
    }
    __syncthreads();
    for (int ii = 0; ii < 8; ii++) {
        int i = i0 + grp * 8 + ii;
        int bi = b * 128 + i;
        if (t < 64) qs[grp][t] = qkv[bi * 1536 + h * 64 + t];
        __syncthreads();
        int j = t;
        float sim = sime[(bi * 128 + j) * 8 + h];
#pragma unroll 16
        for (int d = 0; d < 64; d++) sim += qs[grp][d] * ksm[j * 65 + d];
        sim *= 0.125f;
        float m = sim;
#pragma unroll
        for (int o = 16; o; o >>= 1) m = fmaxf(m, __shfl_xor_sync(0xffffffffu, m, o));
        if (!lane) redm[grp][w] = m;
        __syncthreads();
        m = fmaxf(fmaxf(redm[grp][0], redm[grp][1]), fmaxf(redm[grp][2], redm[grp][3]));
        float ex = expf(sim - m);
        float s = ex;
#pragma unroll
        for (int o = 16; o; o >>= 1) s += __shfl_xor_sync(0xffffffffu, s, o);
        if (!lane) reds[grp][w] = s;
        __syncthreads();
        s = reds[grp][0] + reds[grp][1] + reds[grp][2] + reds[grp][3];
        float a = ex / s;
        attsm[grp][t] = a;
        att[(bi * 8 + h) * 128 + t] = a;
        __syncthreads();
        int gg = t >> 6, d = t & 63;
        float acc = 0.f;
#pragma unroll 16
        for (int jj = 0; jj < 64; jj++)
            acc += attsm[grp][gg * 64 + jj] * vsm[(gg * 64 + jj) * 64 + d];
        psm[grp][t] = acc;
        __syncthreads();
        if (t < 64) aout[bi * 512 + h * 64 + t] = psm[grp][t] + psm[grp][64 + t];
        __syncthreads();
    }
}

// ---------------- edge output: ae = att @ e ; aout += ae @ w_ekv + b_ekv ----------------
__global__ void edgeout_kernel(const float* __restrict__ e, const float* __restrict__ att,
                               const float* __restrict__ wekv, const float* __restrict__ bekv,
                               float* __restrict__ aout) {
    __shared__ float esm[128 * 65];
    __shared__ float asmem[8 * 128];
    __shared__ float aesm[8 * 66];
    int bi = blockIdx.x, tid = threadIdx.x;
    const float* ep = e + (size_t)bi * 8192;
    for (int idx = tid; idx < 8192; idx += 256) {
        int j = idx >> 6, c = idx & 63;
        esm[j * 65 + c] = ep[idx];
    }
    for (int idx = tid; idx < 1024; idx += 256) asmem[idx] = att[bi * 1024 + idx];
    __syncthreads();
    for (int idx = tid; idx < 512; idx += 256) {
        int h = idx >> 6, c = idx & 63;
        float s = 0.f;
#pragma unroll 16
        for (int j = 0; j < 128; j++) s += asmem[h * 128 + j] * esm[j * 65 + c];
        aesm[h * 66 + c] = s;
    }
    __syncthreads();
    for (int idx = tid; idx < 512; idx += 256) {
        int h = idx >> 6, d = idx & 63;
        float s = bekv[idx];
#pragma unroll 16
        for (int c = 0; c < 64; c++) s += aesm[h * 66 + c] * wekv[c * 512 + h * 64 + d];
        aout[bi * 512 + idx] += s;
    }
}

// ---------------- gated residual (in-place) + optional fused LayerNorm ----------------
__global__ void gate_ln_kernel(const float* __restrict__ x, float* __restrict__ nodes,
                               const float* __restrict__ gw,
                               const float* __restrict__ lng, const float* __restrict__ lnb,
                               float* __restrict__ lnout) {
    __shared__ float red[8];
    int row = blockIdx.x, t = threadIdx.x;
    float xv = x[row * 256 + t];
    float rv = nodes[row * 256 + t];
    float contrib = xv * gw[t] + rv * gw[256 + t] + (xv - rv) * gw[512 + t];
    float s = blockSum256(contrib, red);
    float gate = 1.f / (1.f + expf(-s));
    float nn = xv * gate + rv * (1.f - gate);
    nodes[row * 256 + t] = nn;
    if (lng) {
        float m = blockSum256(nn, red) * (1.f / 256.f);
        float d = nn - m;
        float var = blockSum256(d * d, red) * (1.f / 256.f);
        lnout[row * 256 + t] = d * rsqrtf(var + 1e-5f) * lng[t] + lnb[t];
    }
}

// ---------------- codebook squared norms ----------------
__global__ void cnorm_kernel(const float* __restrict__ cb, float* __restrict__ cn) {
    __shared__ float red[8];
    int k = blockIdx.x, t = threadIdx.x;
    float v = cb[k * 256 + t];
    float s = blockSum256(v * v, red);
    if (!t) cn[k] = s;
}

// ---------------- argmin + gather ----------------
__global__ void vq_kernel(const float* __restrict__ S, const float* __restrict__ cn,
                          const float* __restrict__ cb, const float* __restrict__ z,
                          float* __restrict__ out) {
    __shared__ float bv[256];
    __shared__ int bix[256];
    int r = blockIdx.x, t = threadIdx.x;
    float best = 1e30f; int bidx = 0;
    for (int k = t; k < 512; k += 256) {
        float v = cn[k] - 2.f * S[r * 512 + k];
        if (v < best) { best = v; bidx = k; }
    }
    bv[t] = best; bix[t] = bidx;
    __syncthreads();
    for (int s = 128; s; s >>= 1) {
        if (t < s) {
            float v2 = bv[t + s]; int i2 = bix[t + s];
            if (v2 < bv[t] || (v2 == bv[t] && i2 < bix[t])) { bv[t] = v2; bix[t] = i2; }
        }
        __syncthreads();
    }
    int k = bix[0];
    float zz = z[r * 256 + t];
    out[r * 256 + t] = zz + (cb[k * 256 + t] - zz);
}

// ---------------- host launch ----------------
extern "C" void kernel_launch(void* const* d_in, const int* in_sizes, int n_in,
                              void* d_out, int out_size) {
    const float* in_nodes = (const float*)d_in[0];
    const float* edges   = (const float*)d_in[1];
    const float* eg      = (const float*)d_in[2];
    const float* ebias   = (const float*)d_in[3];
    const float* ln1g    = (const float*)d_in[4];
    const float* ln1b    = (const float*)d_in[5];
    const float* wexp    = (const float*)d_in[6];
    const float* bexp    = (const float*)d_in[7];
    const float* wq      = (const float*)d_in[8];
    const float* bq      = (const float*)d_in[9];
    const float* wkv     = (const float*)d_in[10];
    const float* bkv     = (const float*)d_in[11];
    const float* wekv    = (const float*)d_in[12];
    const float* bekv    = (const float*)d_in[13];
    const float* wout    = (const float*)d_in[14];
    const float* bout    = (const float*)d_in[15];
    const float* g1      = (const float*)d_in[16];
    const float* ln2g    = (const float*)d_in[17];
    const float* ln2b    = (const float*)d_in[18];
    const float* wff1    = (const float*)d_in[19];
    const float* bff1    = (const float*)d_in[20];
    const float* wff2    = (const float*)d_in[21];
    const float* bff2    = (const float*)d_in[22];
    const float* g2      = (const float*)d_in[23];
    const float* cb      = (const float*)d_in[24];
    float* out = (float*)d_out;

    float* S;
    cudaGetSymbolAddress((void**)&S, g_scratch);
    float* E     = S + E_OFF;
    float* NODES = S + NODES_OFF;
    float* XN    = S + XN_OFF;
    float* XE    = S + XE_OFF;
    float* QKV   = S + QKV_OFF;
    float* SIME  = S + SIME_OFF;
    float* ATT   = S + ATT_OFF;
    float* AOUT  = S + AOUT_OFF;
    float* OUT2  = S + OUT2_OFF;
    float* H1    = S + H1_OFF;
    float* H2    = S + H2_OFF;
    float* CN    = S + CN_OFF;

    cudaFuncSetAttribute(attn_kernel, cudaFuncAttributeMaxDynamicSharedMemorySize, ATTN_SMEM);

    cudaMemcpyAsync(NODES, in_nodes, (size_t)ROWS * 256 * sizeof(float),
                    cudaMemcpyDeviceToDevice);

    edge_ln_kernel<<<512, 256>>>(edges, eg, ebias, E);
    ln_rows_kernel<<<512, 256>>>(NODES, ln1g, ln1b, XN);

    for (int l = 0; l < 2; l++) {
        // XE = XN @ wexp + bexp          (512x512, K=256)
        gemm_tc<0, 32, 32><<<dim3(16, 16), 128>>>(XN, wexp + l * 131072, nullptr,
                                                  bexp + l * 512, nullptr, XE, 512, 256, 512, 0);
        // QKV = XE @ [wq | wkv] + bias, rotary on Q,K   (512x1536, K=512)
        gemm_tc<2, 32, 64><<<dim3(24, 16), 128>>>(XE, wq + l * 262144, wkv + l * 524288,
                                                  bq + l * 512, bkv + l * 1024, QKV,
                                                  1536, 512, 512, 1024);
        sime_kernel<<<512, 256>>>(E, QKV, wekv + l * 32768, SIME);
        attn_kernel<<<dim3(32, 8), 256, ATTN_SMEM>>>(QKV, SIME, ATT, AOUT);
        edgeout_kernel<<<512, 256>>>(E, ATT, wekv + l * 32768, bekv + l * 512, AOUT);
        // OUT2 = AOUT @ wout + bout      (512x256, K=512)
        gemm_tc<0, 32, 32><<<dim3(8, 16), 128>>>(AOUT, wout + l * 131072, nullptr,
                                                 bout + l * 256, nullptr, OUT2, 256, 512, 256, 0);
        gate_ln_kernel<<<512, 256>>>(OUT2, NODES, g1 + l * 768,
                                     ln2g + l * 256, ln2b + l * 256, XN);
        // H1 = gelu(XN @ wff1 + bff1)    (512x1024, K=256)
        gemm_tc<1, 32, 64><<<dim3(16, 16), 128>>>(XN, wff1 + l * 262144, nullptr,
                                                  bff1 + l * 1024, nullptr, H1, 1024, 256, 1024, 0);
        // H2 = H1 @ wff2 + bff2          (512x256, K=1024)
        gemm_tc<0, 32, 32><<<dim3(8, 16), 128>>>(H1, wff2 + l * 262144, nullptr,
                                                 bff2 + l * 256, nullptr, H2, 256, 1024, 256, 0);
        if (l == 0) {
            gate_ln_kernel<<<512, 256>>>(H2, NODES, g2 + l * 768,
                                         ln1g + 256, ln1b + 256, XN);
        } else {
            gate_ln_kernel<<<512, 256>>>(H2, NODES, g2 + l * 768,
                                         nullptr, nullptr, nullptr);
        }
    }

    cnorm_kernel<<<512, 256>>>(cb, CN);
    // VQ scores: S = NODES @ cb^T via 3xTF32 (fp32-accurate)  (512x512, K=256)
    gemm_vq_tc<<<dim3(8, 8), 128>>>(NODES, cb, XE);
    vq_kernel<<<512, 256>>>(XE, CN, cb, NODES, out);
}